// round 7
// baseline (speedup 1.0000x reference)
#include <cuda_runtime.h>
#include <math.h>
#include <stdint.h>

#define H    160
#define H3   480
#define CC   200
#define TT   20
#define NCH  10
#define NL   160
#define NCLS 16
#define HS   40
#define RPC  120
#define NT   480
#define NBLK 68
#define FLAG_FULL 160

#define NFLAGS ((NL + 1) * NCH + 1)
#define GDONE_IDX ((NL + 1) * NCH)
#define DONE_IDX(l, t) ((l) * NCH + (t))

/* packed weights: g3 wih chunks [0,640), g3 whh chunks [640,1280), branch [1280,1300) */
#define G3_F4   (1280 * 4800)
#define BR_F4   (20 * 9600)
#define PACK_F4 (G3_F4 + BR_F4)

__device__ float4 g_pack[PACK_F4];
__device__ float  g_S[(NL + 1) * NCH * H];
__device__ float  g_xl[H];
__device__ int    g_flags[NFLAGS];

typedef unsigned long long ull;

__device__ __forceinline__ float sigm(float v)   { return __fdividef(1.f, 1.f + __expf(-v)); }
__device__ __forceinline__ float tanh_f(float v) { return __fdividef(2.f, 1.f + __expf(-2.f * v)) - 1.f; }

__device__ __forceinline__ void poll_ge(const int* f, int tgt) {
    int v;
    do {
        asm volatile("ld.acquire.gpu.s32 %0, [%1];" : "=r"(v) : "l"(f) : "memory");
    } while (v < tgt);
}
__device__ __forceinline__ void red_release(int* f) {
    asm volatile("red.release.gpu.add.s32 [%0], %1;" :: "l"(f), "r"(1) : "memory");
}

__device__ __forceinline__ uint32_t smem_u32(const void* p) {
    uint32_t a;
    asm("{ .reg .u64 t; cvta.to.shared.u64 t, %1; cvt.u32.u64 %0, t; }" : "=r"(a) : "l"(p));
    return a;
}
__device__ __forceinline__ void st_cluster_f32(uint32_t laddr, int rank, float v) {
    uint32_t r;
    asm("mapa.shared::cluster.u32 %0, %1, %2;" : "=r"(r) : "r"(laddr), "r"(rank));
    asm volatile("st.shared::cluster.f32 [%0], %1;" :: "r"(r), "f"(v) : "memory");
}
__device__ __forceinline__ void mbar_init(uint32_t addr, uint32_t count) {
    asm volatile("mbarrier.init.shared.b64 [%0], %1;" :: "r"(addr), "r"(count) : "memory");
}
__device__ __forceinline__ void mbar_arrive_rank(uint32_t addr, int rank) {
    uint32_t r;
    asm("mapa.shared::cluster.u32 %0, %1, %2;" : "=r"(r) : "r"(addr), "r"(rank));
    asm volatile("mbarrier.arrive.release.cluster.shared::cluster.b64 _, [%0];" :: "r"(r) : "memory");
}
__device__ __forceinline__ void mbar_wait(uint32_t addr, int parity) {
    asm volatile(
        "{\n\t.reg .pred P;\n\t"
        "WL_%=:\n\t"
        "mbarrier.try_wait.parity.acquire.cluster.shared::cta.b64 P, [%0], %1;\n\t"
        "@!P bra WL_%=;\n\t}"
        :: "r"(addr), "r"(parity) : "memory");
}
#define CLUSTER_SYNC() do { \
    asm volatile("barrier.cluster.arrive.aligned;" ::: "memory"); \
    asm volatile("barrier.cluster.wait.aligned;"   ::: "memory"); } while (0)

__device__ __forceinline__ ull pack2(float x, float y) {
    ull u; asm("mov.b64 %0, {%1, %2};" : "=l"(u) : "f"(x), "f"(y)); return u;
}
__device__ __forceinline__ void fma2(ull& acc, ull a, ull b) {
    asm("fma.rn.f32x2 %0, %1, %2, %0;" : "+l"(acc) : "l"(a), "l"(b));
}
__device__ __forceinline__ float upsum(ull a0, ull a1) {
    float l0, h0, l1, h1;
    asm("mov.b64 {%0, %1}, %2;" : "=f"(l0), "=f"(h0) : "l"(a0));
    asm("mov.b64 {%0, %1}, %2;" : "=f"(l1), "=f"(h1) : "l"(a1));
    return (l0 + h0) + (l1 + h1);
}

/* ---------- pack kernel (also zeroes flags) ---------- */
__global__ void pack_kernel(const float4* __restrict__ wih,
                            const float4* __restrict__ whh,
                            const float4* __restrict__ bwhh) {
    int id = blockIdx.x * blockDim.x + threadIdx.x;
    if (id < NFLAGS) g_flags[id] = 0;
    if (id >= PACK_F4) return;
    float4 v;
    if (id < G3_F4) {
        int m      = id / (640 * 4800);
        int rem    = id - m * (640 * 4800);
        int chunk  = rem / 4800;
        int within = rem - chunk * 4800;
        int i4 = within / 480, tid = within - i4 * 480;
        int l = chunk >> 2, c = chunk & 3;
        int q = tid >> 2, qk = tid & 3;
        int jrow = (q / HS) * H + c * HS + (q % HS);
        int k4 = qk * 10 + i4;
        const float4* src = (m == 0) ? wih : whh;
        v = src[((size_t)l * H3 + jrow) * 40 + k4];
    } else {
        int id2    = id - G3_F4;
        int chunk  = id2 / 9600;
        int within = id2 - chunk * 9600;
        int i4 = within / 480, tid = within - i4 * 480;
        int b = chunk >> 1, hh = chunk & 1;
        int qk2 = tid & 1, gi = tid >> 1;
        int g = gi / 80, ip = gi - g * 80;
        int j = g * H + hh * 80 + ip;
        int k4 = qk2 * 20 + i4;
        v = bwhh[((size_t)b * H3 + j) * 40 + k4];
    }
    g_pack[id] = v;
}

/* ---------- main persistent kernel ---------- */
__global__ void __launch_bounds__(NT, 1) __cluster_dims__(4, 1, 1)
spectral_kernel(
    const float* __restrict__ x,
    const float* __restrict__ b_wih, const float* __restrict__ b_bih,
    const float* __restrict__ b_bhh,
    const float* __restrict__ gw_ih, const float* __restrict__ gw_hh,
    const float* __restrict__ gb_ih, const float* __restrict__ gb_hh,
    const float* __restrict__ g3_bih, const float* __restrict__ g3_bhh,
    const float* __restrict__ bn_gamma, const float* __restrict__ bn_beta,
    const float* __restrict__ bn_mean, const float* __restrict__ bn_var,
    const float* __restrict__ fc_w, const float* __restrict__ fc_b,
    const float* __restrict__ reg_w, const float* __restrict__ reg_b,
    float* __restrict__ out)
{
    extern __shared__ float sm[];
    const int tid = threadIdx.x;
    const int blk = blockIdx.x;
    const float4* packW = g_pack;

    /* ============ g3 wavefront: blocks 0..39 (cluster = time group) ======== */
    if (blk < 40) {
        const int t = blk >> 2;
        const int c = blk & 3;
        const int q  = tid >> 2;
        const int qk = tid & 3;
        const int jrow = (q / HS) * H + c * HS + (q % HS);

        const uint32_t mb0 = smem_u32(sm);     /* two mbarriers: 16 bytes */
        float* xin2 = sm + 4;              /* [2][H] */
        float* xps  = xin2 + 2 * H;        /* [RPC]  */
        float* hps  = xps + RPC;           /* [RPC]  */
        const uint32_t xin_base = smem_u32(xin2);

        if (tid == 0) { mbar_init(mb0, FLAG_FULL); mbar_init(mb0 + 8, FLAG_FULL); }
        __syncthreads();
        CLUSTER_SYNC();

        ull Wx[20], Wh[20];
        {   /* preload wih(0) */
            size_t base = (size_t)(0 * 4 + c) * 4800 + tid;
#pragma unroll
            for (int i4 = 0; i4 < 10; ++i4) {
                float4 f = __ldg(&packW[base + i4 * 480]);
                Wx[2 * i4] = pack2(f.x, f.y); Wx[2 * i4 + 1] = pack2(f.z, f.w);
            }
        }

        poll_ge(&g_flags[DONE_IDX(0, t)], FLAG_FULL);
        if (tid < 40)
            *(float4*)&xin2[tid * 4] = __ldcg((const float4*)&g_S[t * H + tid * 4]);
        __syncthreads();

        for (int l = 0; l < NL; ++l) {
            const int cur = l & 1, nxt = cur ^ 1;
            float bih_v = 0.f, bhh_v = 0.f;
            if (qk == 0) { bih_v = __ldg(&g3_bih[l * H3 + jrow]); bhh_v = __ldg(&g3_bhh[l * H3 + jrow]); }

            {   /* preload whh(l) */
                size_t base = (size_t)(640 + l * 4 + c) * 4800 + tid;
#pragma unroll
                for (int i4 = 0; i4 < 10; ++i4) {
                    float4 f = __ldg(&packW[base + i4 * 480]);
                    Wh[2 * i4] = pack2(f.x, f.y); Wh[2 * i4 + 1] = pack2(f.z, f.w);
                }
            }

            /* wait for completion of layer l-1 on barrier (l-1)&1 */
            if (l > 0) mbar_wait(mb0 + (uint32_t)(((l - 1) & 1) * 8), ((l - 1) >> 1) & 1);

            /* phase X */
            {
                const float* xv = xin2 + cur * H + qk * HS;
                ull a0 = 0, a1 = 0;
#pragma unroll
                for (int i4 = 0; i4 < 10; ++i4) {
                    ulonglong2 hv = *(const ulonglong2*)(xv + i4 * 4);
                    fma2(a0, Wx[2 * i4], hv.x);
                    fma2(a1, Wx[2 * i4 + 1], hv.y);
                }
                float a = upsum(a0, a1);
                a += __shfl_xor_sync(0xffffffffu, a, 1);
                a += __shfl_xor_sync(0xffffffffu, a, 2);
                if (qk == 0) xps[q] = a + bih_v;
            }

            /* preload wih(l+1) */
            if (l + 1 < NL) {
                size_t base = (size_t)((l + 1) * 4 + c) * 4800 + tid;
#pragma unroll
                for (int i4 = 0; i4 < 10; ++i4) {
                    float4 f = __ldg(&packW[base + i4 * 480]);
                    Wx[2 * i4] = pack2(f.x, f.y); Wx[2 * i4 + 1] = pack2(f.z, f.w);
                }
            }

            /* phase H: h_prev straight from L2 */
            if (t > 0) {
                poll_ge(&g_flags[DONE_IDX(l + 1, t - 1)], FLAG_FULL);
                const float4* hvp =
                    (const float4*)(g_S + ((size_t)(l + 1) * NCH + (t - 1)) * H + qk * HS);
                ull a0 = 0, a1 = 0;
#pragma unroll
                for (int i4 = 0; i4 < 10; ++i4) {
                    float4 f = __ldcg(hvp + i4);
                    fma2(a0, Wh[2 * i4], pack2(f.x, f.y));
                    fma2(a1, Wh[2 * i4 + 1], pack2(f.z, f.w));
                }
                float a = upsum(a0, a1);
                a += __shfl_xor_sync(0xffffffffu, a, 1);
                a += __shfl_xor_sync(0xffffffffu, a, 2);
                if (qk == 0) hps[q] = a + bhh_v;
            } else {
                if (qk == 0) hps[q] = bhh_v;
            }
            __syncthreads();          /* the only per-layer CTA barrier */

            /* gate + publish (threads qk==0, q<40) -> arrive on barrier l&1 */
            if (qk == 0 && q < HS) {
                const int i = q;
                float hp_i = 0.f;
                if (t > 0) hp_i = __ldcg(&g_S[((size_t)(l + 1) * NCH + (t - 1)) * H + c * HS + i]);
                float r = sigm(xps[i]          + hps[i]);
                float z = sigm(xps[HS + i]     + hps[HS + i]);
                float n = tanh_f(xps[2*HS + i] + r * hps[2*HS + i]);
                float hn = (1.f - z) * n + z * hp_i;
                __stcg(&g_S[((size_t)(l + 1) * NCH + t) * H + c * HS + i], hn);
                red_release(&g_flags[DONE_IDX(l + 1, t)]);
                uint32_t a3 = xin_base + (uint32_t)(nxt * H + c * HS + i) * 4u;
#pragma unroll
                for (int r2 = 0; r2 < 4; ++r2) st_cluster_f32(a3, r2, hn);
                uint32_t mbl = mb0 + (uint32_t)((l & 1) * 8);
#pragma unroll
                for (int r2 = 0; r2 < 4; ++r2) mbar_arrive_rank(mbl, r2);
            }
        }
        /* drain: ensure all remote stores/arrives to THIS CTA have landed before exit */
        mbar_wait(mb0 + (uint32_t)(((NL - 1) & 1) * 8), ((NL - 1) >> 1) & 1);
        return;
    }

    /* ============ global GRU: blocks 40..43, one cluster =================== */
    if (blk < 44) {
        const int c = blk - 40;
        const int PAD = 164;

        const uint32_t mb0 = smem_u32(sm);
        float* whh_s = sm + 4;                   /* [RPC*PAD] */
        float* xp_s  = whh_s + RPC * PAD;        /* [CC*RPC]  */
        float* bhh_s = xp_s + CC * RPC;          /* [RPC]     */
        float* h2    = bhh_s + RPC;              /* [2][H]    */
        float* hpb   = h2 + 2 * H;               /* [RPC]     */
        const uint32_t h2_base = smem_u32(h2);

        if (tid == 0) { mbar_init(mb0, FLAG_FULL); mbar_init(mb0 + 8, FLAG_FULL); }

        for (int idx = tid; idx < RPC * H; idx += NT) {
            int q2 = idx / H, k = idx - q2 * H;
            int j = (q2 / HS) * H + c * HS + (q2 % HS);
            whh_s[q2 * PAD + k] = gw_hh[(size_t)j * H + k];
        }
        for (int idx = tid; idx < CC * RPC; idx += NT) {
            int s = idx / RPC, q2 = idx - s * RPC;
            int j = (q2 / HS) * H + c * HS + (q2 % HS);
            xp_s[s * RPC + q2] = x[s] * gw_ih[j] + gb_ih[j];
        }
        if (tid < RPC) {
            int j = (tid / HS) * H + c * HS + (tid % HS);
            bhh_s[tid] = gb_hh[j];
        }
        if (tid < 2 * H) h2[tid] = 0.f;
        __syncthreads();
        CLUSTER_SYNC();

        const int q2 = tid >> 2;
        const int qk = tid & 3;
        float hsum = 0.f;

        for (int s = 0; s < CC; ++s) {
            const int cur = s & 1, nxt = cur ^ 1;
            if (s > 0) mbar_wait(mb0 + (uint32_t)(((s - 1) & 1) * 8), ((s - 1) >> 1) & 1);

            const float* wr = whh_s + q2 * PAD + qk;
            const float* hv = h2 + cur * H + qk;
            float a0 = 0.f, a1 = 0.f;
#pragma unroll
            for (int i = 0; i < HS; i += 2) {
                a0 += wr[(i + 0) * 4] * hv[(i + 0) * 4];
                a1 += wr[(i + 1) * 4] * hv[(i + 1) * 4];
            }
            float a = a0 + a1;
            a += __shfl_xor_sync(0xffffffffu, a, 1);
            a += __shfl_xor_sync(0xffffffffu, a, 2);
            if (qk == 0) hpb[q2] = a + bhh_s[q2];
            __syncthreads();

            if (tid < HS) {
                const float* xpt = xp_s + s * RPC;
                float r = sigm(xpt[tid]          + hpb[tid]);
                float z = sigm(xpt[HS + tid]     + hpb[HS + tid]);
                float n = tanh_f(xpt[2*HS + tid] + r * hpb[2*HS + tid]);
                float hn = (1.f - z) * n + z * h2[cur * H + c * HS + tid];
                hsum += hn;
                uint32_t a2 = h2_base + (uint32_t)(nxt * H + c * HS + tid) * 4u;
#pragma unroll
                for (int r2 = 0; r2 < 4; ++r2) st_cluster_f32(a2, r2, hn);
                uint32_t mbs = mb0 + (uint32_t)((s & 1) * 8);
#pragma unroll
                for (int r2 = 0; r2 < 4; ++r2) mbar_arrive_rank(mbs, r2);
            }
        }
        /* drain before any exit */
        mbar_wait(mb0 + (uint32_t)(((CC - 1) & 1) * 8), ((CC - 1) >> 1) & 1);
        if (tid < HS) {
            __stcg(&g_xl[c * HS + tid], hsum * (1.f / CC));
            red_release(&g_flags[GDONE_IDX]);
        }
        return;
    }

    /* ============ branch GRUs: blocks 44..63 (2 CTAs per branch) =========== */
    if (blk < 64) {
        const int pairblk = blk - 44;
        const int b    = pairblk >> 1;
        const int hh   = pairblk & 1;
        const int rank = pairblk & 3;

        const uint32_t mb0 = smem_u32(sm);
        float* xp_s = sm + 4;                  /* [TT*240]  */
        float* h2   = xp_s + TT * 240;         /* [2][H]    */
        float* hp_s = h2 + 2 * H;              /* [240]     */
        const uint32_t h2b = smem_u32(h2);

        if (tid == 0) { mbar_init(mb0, FLAG_FULL); mbar_init(mb0 + 8, FLAG_FULL); }

        const int qk2 = tid & 1;
        const int gi  = tid >> 1;
        const int g   = gi / 80;
        const int ip  = gi - g * 80;
        const int jrow = g * H + hh * 80 + ip;

        ull W[40];
        {
            size_t base = (size_t)G3_F4 + (size_t)(b * 2 + hh) * 9600 + tid;
#pragma unroll
            for (int i4 = 0; i4 < 20; ++i4) {
                float4 f = __ldg(&packW[base + i4 * 480]);
                W[2 * i4] = pack2(f.x, f.y); W[2 * i4 + 1] = pack2(f.z, f.w);
            }
        }
        float bhh_v = 0.f;
        if (qk2 == 0) bhh_v = __ldg(&b_bhh[b * H3 + jrow]);

        for (int idx = tid; idx < TT * 240; idx += NT) {
            int tt = idx / 240, lr = idx - tt * 240;
            int j = (lr / 80) * H + hh * 80 + (lr % 80);
            xp_s[idx] = x[b * TT + tt] * b_wih[b * H3 + j] + b_bih[b * H3 + j];
        }
        if (tid < 2 * H) h2[tid] = 0.f;
        __syncthreads();
        CLUSTER_SYNC();

        for (int tt = 0; tt < TT; ++tt) {
            const int cur = tt & 1, nxt = cur ^ 1;
            if (tt > 0) mbar_wait(mb0 + (uint32_t)(((tt - 1) & 1) * 8), ((tt - 1) >> 1) & 1);

            const float* hv0 = h2 + cur * H + qk2 * 80;
            ull a0 = 0, a1 = 0;
#pragma unroll
            for (int i4 = 0; i4 < 20; ++i4) {
                ulonglong2 hv = *(const ulonglong2*)(hv0 + i4 * 4);
                fma2(a0, W[2 * i4], hv.x);
                fma2(a1, W[2 * i4 + 1], hv.y);
            }
            float a = upsum(a0, a1);
            a += __shfl_xor_sync(0xffffffffu, a, 1);
            if (qk2 == 0) hp_s[g * 80 + ip] = a + bhh_v;
            __syncthreads();

            if (qk2 == 0 && gi < 80) {
                const int i = gi;
                const float* xpt = xp_s + tt * 240;
                float r = sigm(xpt[i]          + hp_s[i]);
                float z = sigm(xpt[80 + i]     + hp_s[80 + i]);
                float n = tanh_f(xpt[160 + i]  + r * hp_s[160 + i]);
                float hn = (1.f - z) * n + z * h2[cur * H + hh * 80 + i];
                uint32_t a3 = h2b + (uint32_t)(nxt * H + hh * 80 + i) * 4u;
                st_cluster_f32(a3, rank, hn);
                st_cluster_f32(a3, rank ^ 1, hn);
                uint32_t mbt = mb0 + (uint32_t)((tt & 1) * 8);
                mbar_arrive_rank(mbt, rank);
                mbar_arrive_rank(mbt, rank ^ 1);
            }
        }
        /* drain */
        mbar_wait(mb0 + (uint32_t)(((TT - 1) & 1) * 8), ((TT - 1) >> 1) & 1);
        if (tid < 80) {
            __stcg(&g_S[b * H + hh * 80 + tid], h2[0 * H + hh * 80 + tid]);
            red_release(&g_flags[DONE_IDX(0, b)]);
        }
        return;
    }

    /* ============ epilogue: block 64 (65..67 idle) ========================= */
    if (blk == 64) {
        for (int tt = 0; tt < NCH; ++tt) poll_ge(&g_flags[DONE_IDX(NL, tt)], FLAG_FULL);
        poll_ge(&g_flags[GDONE_IDX], FLAG_FULL);

        float* xr = sm;
        if (tid < H) {
            float m = 0.f;
#pragma unroll
            for (int tt = 0; tt < NCH; ++tt) m += __ldcg(&g_S[(NL * NCH + tt) * H + tid]);
            m *= (1.f / NCH);
            m = fmaxf(m, 0.f);
            float xnew = __ldcg(&g_xl[tid]) * m;
            float xb = (xnew - bn_mean[tid]) * rsqrtf(bn_var[tid] + 1e-5f)
                       * bn_gamma[tid] + bn_beta[tid];
            xr[tid] = fmaxf(xb, 0.f);
        }
        __syncthreads();

        if (tid < NCLS + CC) {
            const float* wrow; float bias;
            if (tid < NCLS) { wrow = fc_w + tid * H;           bias = fc_b[tid]; }
            else            { wrow = reg_w + (tid - NCLS) * H; bias = reg_b[tid - NCLS]; }
            float a = bias;
#pragma unroll 10
            for (int k = 0; k < H; ++k) a += wrow[k] * xr[k];
            out[tid] = a;
        }
        return;
    }
}

extern "C" void kernel_launch(void* const* d_in, const int* in_sizes, int n_in,
                              void* d_out, int out_size) {
    const float* x        = (const float*)d_in[0];
    const float* b_wih    = (const float*)d_in[1];
    const float* b_whh    = (const float*)d_in[2];
    const float* b_bih    = (const float*)d_in[3];
    const float* b_bhh    = (const float*)d_in[4];
    const float* gw_ih    = (const float*)d_in[5];
    const float* gw_hh    = (const float*)d_in[6];
    const float* gb_ih    = (const float*)d_in[7];
    const float* gb_hh    = (const float*)d_in[8];
    const float* g3_wih   = (const float*)d_in[9];
    const float* g3_whh   = (const float*)d_in[10];
    const float* g3_bih   = (const float*)d_in[11];
    const float* g3_bhh   = (const float*)d_in[12];
    const float* bn_gamma = (const float*)d_in[13];
    const float* bn_beta  = (const float*)d_in[14];
    const float* bn_mean  = (const float*)d_in[15];
    const float* bn_var   = (const float*)d_in[16];
    const float* fc_w     = (const float*)d_in[17];
    const float* fc_b     = (const float*)d_in[18];
    const float* reg_w    = (const float*)d_in[19];
    const float* reg_b    = (const float*)d_in[20];
    float* out = (float*)d_out;

    const int smem_bytes = (4 + RPC * 164 + CC * RPC + RPC + 2 * H + RPC) * (int)sizeof(float);
    cudaFuncSetAttribute(spectral_kernel,
                         cudaFuncAttributeMaxDynamicSharedMemorySize, smem_bytes);

    pack_kernel<<<(PACK_F4 + 255) / 256, 256>>>(
        (const float4*)g3_wih, (const float4*)g3_whh, (const float4*)b_whh);
    spectral_kernel<<<NBLK, NT, smem_bytes>>>(
        x, b_wih, b_bih, b_bhh,
        gw_ih, gw_hh, gb_ih, gb_hh,
        g3_bih, g3_bhh,
        bn_gamma, bn_beta, bn_mean, bn_var,
        fc_w, fc_b, reg_w, reg_b, out);
}

// round 8
// speedup vs baseline: 1.4061x; 1.4061x over previous
#include <cuda_runtime.h>
#include <math.h>
#include <stdint.h>

#define H    160
#define H3   480
#define CC   200
#define TT   20
#define NCH  10
#define NL   160
#define NCLS 16
#define HS   40
#define RPC  120
#define NT   480
#define NBLK 68
#define FULL 160

#define NFLAGS ((NL + 1) * NCH + 1)
#define GDONE_IDX ((NL + 1) * NCH)
#define DONE_IDX(l, t) ((l) * NCH + (t))

/* packed weights: g3 wih chunks [0,640), g3 whh chunks [640,1280), branch [1280,1300) */
#define G3_F4   (1280 * 4800)
#define BR_F4   (20 * 9600)
#define PACK_F4 (G3_F4 + BR_F4)

__device__ float4 g_pack[PACK_F4];
__device__ float  g_S[(NL + 1) * NCH * H];
__device__ float  g_xl[H];
__device__ int    g_flags[NFLAGS];

typedef unsigned long long ull;

__device__ __forceinline__ float sigm(float v)   { return __fdividef(1.f, 1.f + __expf(-v)); }
__device__ __forceinline__ float tanh_f(float v) { return __fdividef(2.f, 1.f + __expf(-2.f * v)) - 1.f; }

__device__ __forceinline__ void poll_ge(const int* f, int tgt) {
    int v;
    do {
        asm volatile("ld.acquire.gpu.s32 %0, [%1];" : "=r"(v) : "l"(f) : "memory");
    } while (v < tgt);
}
__device__ __forceinline__ void red_release(int* f, int val) {
    asm volatile("red.release.gpu.add.s32 [%0], %1;" :: "l"(f), "r"(val) : "memory");
}

__device__ __forceinline__ uint32_t smem_u32(const void* p) {
    uint32_t a;
    asm("{ .reg .u64 t; cvta.to.shared.u64 t, %1; cvt.u32.u64 %0, t; }" : "=r"(a) : "l"(p));
    return a;
}
__device__ __forceinline__ void st_cluster_f32(uint32_t laddr, int rank, float v) {
    uint32_t r;
    asm("mapa.shared::cluster.u32 %0, %1, %2;" : "=r"(r) : "r"(laddr), "r"(rank));
    asm volatile("st.shared::cluster.f32 [%0], %1;" :: "r"(r), "f"(v) : "memory");
}
#define CLUSTER_SYNC() do { \
    asm volatile("barrier.cluster.arrive.aligned;" ::: "memory"); \
    asm volatile("barrier.cluster.wait.aligned;"   ::: "memory"); } while (0)

__device__ __forceinline__ ull pack2(float x, float y) {
    ull u; asm("mov.b64 %0, {%1, %2};" : "=l"(u) : "f"(x), "f"(y)); return u;
}
__device__ __forceinline__ void fma2(ull& acc, ull a, ull b) {
    asm("fma.rn.f32x2 %0, %1, %2, %0;" : "+l"(acc) : "l"(a), "l"(b));
}
__device__ __forceinline__ float upsum(ull a0, ull a1) {
    float l0, h0, l1, h1;
    asm("mov.b64 {%0, %1}, %2;" : "=f"(l0), "=f"(h0) : "l"(a0));
    asm("mov.b64 {%0, %1}, %2;" : "=f"(l1), "=f"(h1) : "l"(a1));
    return (l0 + h0) + (l1 + h1);
}

/* ---------- pack kernel (also zeroes flags) ---------- */
__global__ void pack_kernel(const float4* __restrict__ wih,
                            const float4* __restrict__ whh,
                            const float4* __restrict__ bwhh) {
    int id = blockIdx.x * blockDim.x + threadIdx.x;
    if (id < NFLAGS) g_flags[id] = 0;
    if (id >= PACK_F4) return;
    float4 v;
    if (id < G3_F4) {
        int m      = id / (640 * 4800);
        int rem    = id - m * (640 * 4800);
        int chunk  = rem / 4800;
        int within = rem - chunk * 4800;
        int i4 = within / 480, tid = within - i4 * 480;
        int l = chunk >> 2, c = chunk & 3;
        int q = tid >> 2, qk = tid & 3;
        int jrow = (q / HS) * H + c * HS + (q % HS);
        int k4 = qk * 10 + i4;
        const float4* src = (m == 0) ? wih : whh;
        v = src[((size_t)l * H3 + jrow) * 40 + k4];
    } else {
        int id2    = id - G3_F4;
        int chunk  = id2 / 9600;
        int within = id2 - chunk * 9600;
        int i4 = within / 480, tid = within - i4 * 480;
        int b = chunk >> 1, hh = chunk & 1;
        int qk2 = tid & 1, gi = tid >> 1;
        int g = gi / 80, ip = gi - g * 80;
        int j = g * H + hh * 80 + ip;
        int k4 = qk2 * 20 + i4;
        v = bwhh[((size_t)b * H3 + j) * 40 + k4];
    }
    g_pack[id] = v;
}

/* ---------- main persistent kernel ---------- */
__global__ void __launch_bounds__(NT, 1) __cluster_dims__(4, 1, 1)
spectral_kernel(
    const float* __restrict__ x,
    const float* __restrict__ b_wih, const float* __restrict__ b_bih,
    const float* __restrict__ b_bhh,
    const float* __restrict__ gw_ih, const float* __restrict__ gw_hh,
    const float* __restrict__ gb_ih, const float* __restrict__ gb_hh,
    const float* __restrict__ g3_bih, const float* __restrict__ g3_bhh,
    const float* __restrict__ bn_gamma, const float* __restrict__ bn_beta,
    const float* __restrict__ bn_mean, const float* __restrict__ bn_var,
    const float* __restrict__ fc_w, const float* __restrict__ fc_b,
    const float* __restrict__ reg_w, const float* __restrict__ reg_b,
    float* __restrict__ out)
{
    extern __shared__ float sm[];
    const int tid = threadIdx.x;
    const int blk = blockIdx.x;
    const float4* packW = g_pack;

    /* ============ g3 wavefront: blocks 0..39 (cluster = time group) ======== */
    if (blk < 40) {
        const int t = blk >> 2;
        const int c = blk & 3;
        const int q  = tid >> 2;
        const int qk = tid & 3;
        const int jrow = (q / HS) * H + c * HS + (q % HS);

        float* xin2  = sm;                 /* [2][H] */
        float* hprev = sm + 2 * H;         /* [H]    */
        float* xps   = sm + 3 * H;         /* [RPC]  */
        float* hps   = xps + RPC;          /* [RPC]  */
        const uint32_t xin_base = smem_u32(xin2);

        CLUSTER_SYNC();   /* siblings alive before any DSMEM store */

        ull Wx[20], Wh[20];
        {   /* preload wih(0) */
            size_t base = (size_t)(0 * 4 + c) * 4800 + tid;
#pragma unroll
            for (int i4 = 0; i4 < 10; ++i4) {
                float4 f = __ldg(&packW[base + i4 * 480]);
                Wx[2 * i4] = pack2(f.x, f.y); Wx[2 * i4 + 1] = pack2(f.z, f.w);
            }
        }

        /* l=0 input: branch t output from L2 */
        if (tid < 40) {
            poll_ge(&g_flags[DONE_IDX(0, t)], FULL);
            *(float4*)&xin2[tid * 4] = __ldcg((const float4*)&g_S[t * H + tid * 4]);
        }
        __syncthreads();

        for (int l = 0; l < NL; ++l) {
            const int cur = l & 1, nxt = cur ^ 1;
            float bih_v = 0.f, bhh_v = 0.f;
            if (qk == 0) { bih_v = __ldg(&g3_bih[l * H3 + jrow]); bhh_v = __ldg(&g3_bhh[l * H3 + jrow]); }

            {   /* preload whh(l) */
                size_t base = (size_t)(640 + l * 4 + c) * 4800 + tid;
#pragma unroll
                for (int i4 = 0; i4 < 10; ++i4) {
                    float4 f = __ldg(&packW[base + i4 * 480]);
                    Wh[2 * i4] = pack2(f.x, f.y); Wh[2 * i4 + 1] = pack2(f.z, f.w);
                }
            }

            /* wait xin2[cur] complete (covers siblings' DSMEM gate stores of l-1) */
            if (l > 0) {
                if (tid < 40) poll_ge(&g_flags[DONE_IDX(l, t)], FULL);
                __syncthreads();                               /* B1 */
            }

            /* phase X */
            {
                const float* xv = xin2 + cur * H + qk * HS;
                ull a0 = 0, a1 = 0;
#pragma unroll
                for (int i4 = 0; i4 < 10; ++i4) {
                    ulonglong2 hv = *(const ulonglong2*)(xv + i4 * 4);
                    fma2(a0, Wx[2 * i4], hv.x);
                    fma2(a1, Wx[2 * i4 + 1], hv.y);
                }
                float a = upsum(a0, a1);
                a += __shfl_xor_sync(0xffffffffu, a, 1);
                a += __shfl_xor_sync(0xffffffffu, a, 2);
                if (qk == 0) xps[q] = a + bih_v;
            }

            /* preload wih(l+1) */
            if (l + 1 < NL) {
                size_t base = (size_t)((l + 1) * 4 + c) * 4800 + tid;
#pragma unroll
                for (int i4 = 0; i4 < 10; ++i4) {
                    float4 f = __ldg(&packW[base + i4 * 480]);
                    Wx[2 * i4] = pack2(f.x, f.y); Wx[2 * i4 + 1] = pack2(f.z, f.w);
                }
            }

            /* poll + stage h_prev, then phase H */
            if (t > 0) {
                if (tid < 40) {
                    poll_ge(&g_flags[DONE_IDX(l + 1, t - 1)], FULL);
                    *(float4*)&hprev[tid * 4] =
                        __ldcg((const float4*)&g_S[((size_t)(l + 1) * NCH + (t - 1)) * H + tid * 4]);
                }
                __syncthreads();                               /* B2 */
                const float* hv0 = hprev + qk * HS;
                ull a0 = 0, a1 = 0;
#pragma unroll
                for (int i4 = 0; i4 < 10; ++i4) {
                    ulonglong2 hv = *(const ulonglong2*)(hv0 + i4 * 4);
                    fma2(a0, Wh[2 * i4], hv.x);
                    fma2(a1, Wh[2 * i4 + 1], hv.y);
                }
                float a = upsum(a0, a1);
                a += __shfl_xor_sync(0xffffffffu, a, 1);
                a += __shfl_xor_sync(0xffffffffu, a, 2);
                if (qk == 0) hps[q] = a + bhh_v;
            } else {
                if (qk == 0) hps[q] = bhh_v;
            }
            __syncthreads();                                   /* B3 */

            /* gate + publish (40 threads, qk==0 && q<40) */
            if (qk == 0 && q < HS) {
                const int i = q;
                float hp_i = (t > 0) ? hprev[c * HS + i] : 0.f;
                float r = sigm(xps[i]          + hps[i]);
                float z = sigm(xps[HS + i]     + hps[HS + i]);
                float n = tanh_f(xps[2*HS + i] + r * hps[2*HS + i]);
                float hn = (1.f - z) * n + z * hp_i;
                __stcg(&g_S[((size_t)(l + 1) * NCH + t) * H + c * HS + i], hn);
                uint32_t a3 = xin_base + (uint32_t)(nxt * H + c * HS + i) * 4u;
#pragma unroll
                for (int r2 = 0; r2 < 4; ++r2) st_cluster_f32(a3, r2, hn);
                red_release(&g_flags[DONE_IDX(l + 1, t)], 1);
            }
            /* next iteration's B1 orders gate-readers vs phase-X writers */
        }
        CLUSTER_SYNC();   /* drain remote DSMEM stores before exit */
        return;
    }

    /* ============ global GRU: blocks 40..43, one cluster =================== */
    if (blk < 44) {
        const int c = blk - 40;
        const int PAD = 164;

        float* whh_s = sm;                       /* [RPC*PAD] */
        float* xp_s  = whh_s + RPC * PAD;        /* [CC*RPC]  */
        float* bhh_s = xp_s + CC * RPC;          /* [RPC]     */
        float* h2    = bhh_s + RPC;              /* [2][H]    */
        float* hpb   = h2 + 2 * H;               /* [RPC]     */
        const uint32_t h2_base = smem_u32(h2);

        for (int idx = tid; idx < RPC * H; idx += NT) {
            int q2 = idx / H, k = idx - q2 * H;
            int j = (q2 / HS) * H + c * HS + (q2 % HS);
            whh_s[q2 * PAD + k] = gw_hh[(size_t)j * H + k];
        }
        for (int idx = tid; idx < CC * RPC; idx += NT) {
            int s = idx / RPC, q2 = idx - s * RPC;
            int j = (q2 / HS) * H + c * HS + (q2 % HS);
            xp_s[s * RPC + q2] = x[s] * gw_ih[j] + gb_ih[j];
        }
        if (tid < RPC) {
            int j = (tid / HS) * H + c * HS + (tid % HS);
            bhh_s[tid] = gb_hh[j];
        }
        if (tid < 2 * H) h2[tid] = 0.f;
        __syncthreads();
        CLUSTER_SYNC();

        const int q2 = tid >> 2;
        const int qk = tid & 3;
        float hsum = 0.f;

        for (int s = 0; s < CC; ++s) {
            const int cur = s & 1, nxt = cur ^ 1;
            const float* wr = whh_s + q2 * PAD + qk;
            const float* hv = h2 + cur * H + qk;
            float a0 = 0.f, a1 = 0.f;
#pragma unroll
            for (int i = 0; i < HS; i += 2) {
                a0 += wr[(i + 0) * 4] * hv[(i + 0) * 4];
                a1 += wr[(i + 1) * 4] * hv[(i + 1) * 4];
            }
            float a = a0 + a1;
            a += __shfl_xor_sync(0xffffffffu, a, 1);
            a += __shfl_xor_sync(0xffffffffu, a, 2);
            if (qk == 0) hpb[q2] = a + bhh_s[q2];
            __syncthreads();

            if (tid < HS) {
                const float* xpt = xp_s + s * RPC;
                float r = sigm(xpt[tid]          + hpb[tid]);
                float z = sigm(xpt[HS + tid]     + hpb[HS + tid]);
                float n = tanh_f(xpt[2*HS + tid] + r * hpb[2*HS + tid]);
                float hn = (1.f - z) * n + z * h2[cur * H + c * HS + tid];
                hsum += hn;
                uint32_t a2 = h2_base + (uint32_t)(nxt * H + c * HS + tid) * 4u;
#pragma unroll
                for (int r2 = 0; r2 < 4; ++r2) st_cluster_f32(a2, r2, hn);
            }
            CLUSTER_SYNC();
        }
        if (tid < HS) {
            __stcg(&g_xl[c * HS + tid], hsum * (1.f / CC));
            red_release(&g_flags[GDONE_IDX], 4);
        }
        return;
    }

    /* ============ branch GRUs: blocks 44..63 (2 CTAs per branch) =========== */
    if (blk < 64) {
        const int pairblk = blk - 44;
        const int b    = pairblk >> 1;
        const int hh   = pairblk & 1;
        const int rank = pairblk & 3;

        float* xp_s = sm;                      /* [TT*240]  */
        float* h2   = xp_s + TT * 240;         /* [2][H]    */
        float* hp_s = h2 + 2 * H;              /* [240]     */
        const uint32_t h2b = smem_u32(h2);

        const int qk2 = tid & 1;
        const int gi  = tid >> 1;
        const int g   = gi / 80;
        const int ip  = gi - g * 80;
        const int jrow = g * H + hh * 80 + ip;

        ull W[40];
        {
            size_t base = (size_t)G3_F4 + (size_t)(b * 2 + hh) * 9600 + tid;
#pragma unroll
            for (int i4 = 0; i4 < 20; ++i4) {
                float4 f = __ldg(&packW[base + i4 * 480]);
                W[2 * i4] = pack2(f.x, f.y); W[2 * i4 + 1] = pack2(f.z, f.w);
            }
        }
        float bhh_v = 0.f;
        if (qk2 == 0) bhh_v = __ldg(&b_bhh[b * H3 + jrow]);

        for (int idx = tid; idx < TT * 240; idx += NT) {
            int tt = idx / 240, lr = idx - tt * 240;
            int j = (lr / 80) * H + hh * 80 + (lr % 80);
            xp_s[idx] = x[b * TT + tt] * b_wih[b * H3 + j] + b_bih[b * H3 + j];
        }
        if (tid < 2 * H) h2[tid] = 0.f;
        __syncthreads();
        CLUSTER_SYNC();

        for (int tt = 0; tt < TT; ++tt) {
            const int cur = tt & 1, nxt = cur ^ 1;
            const float* hv0 = h2 + cur * H + qk2 * 80;
            ull a0 = 0, a1 = 0;
#pragma unroll
            for (int i4 = 0; i4 < 20; ++i4) {
                ulonglong2 hv = *(const ulonglong2*)(hv0 + i4 * 4);
                fma2(a0, W[2 * i4], hv.x);
                fma2(a1, W[2 * i4 + 1], hv.y);
            }
            float a = upsum(a0, a1);
            a += __shfl_xor_sync(0xffffffffu, a, 1);
            if (qk2 == 0) hp_s[g * 80 + ip] = a + bhh_v;
            __syncthreads();

            if (qk2 == 0 && gi < 80) {
                const int i = gi;
                const float* xpt = xp_s + tt * 240;
                float r = sigm(xpt[i]          + hp_s[i]);
                float z = sigm(xpt[80 + i]     + hp_s[80 + i]);
                float n = tanh_f(xpt[160 + i]  + r * hp_s[160 + i]);
                float hn = (1.f - z) * n + z * h2[cur * H + hh * 80 + i];
                uint32_t a3 = h2b + (uint32_t)(nxt * H + hh * 80 + i) * 4u;
                st_cluster_f32(a3, rank, hn);
                st_cluster_f32(a3, rank ^ 1, hn);
            }
            CLUSTER_SYNC();
        }
        if (tid < 80) {
            __stcg(&g_S[b * H + hh * 80 + tid], h2[0 * H + hh * 80 + tid]);
            red_release(&g_flags[DONE_IDX(0, b)], 1);
        }
        CLUSTER_SYNC();
        return;
    }

    /* ============ epilogue: block 64 (65..67 idle) ========================= */
    if (blk == 64) {
        if (tid == 0) {
            for (int tt = 0; tt < NCH; ++tt) poll_ge(&g_flags[DONE_IDX(NL, tt)], FULL);
            poll_ge(&g_flags[GDONE_IDX], FULL);
        }
        __syncthreads();

        float* xr = sm;
        if (tid < H) {
            float m = 0.f;
#pragma unroll
            for (int tt = 0; tt < NCH; ++tt) m += __ldcg(&g_S[(NL * NCH + tt) * H + tid]);
            m *= (1.f / NCH);
            m = fmaxf(m, 0.f);
            float xnew = __ldcg(&g_xl[tid]) * m;
            float xb = (xnew - bn_mean[tid]) * rsqrtf(bn_var[tid] + 1e-5f)
                       * bn_gamma[tid] + bn_beta[tid];
            xr[tid] = fmaxf(xb, 0.f);
        }
        __syncthreads();

        if (tid < NCLS + CC) {
            const float* wrow; float bias;
            if (tid < NCLS) { wrow = fc_w + tid * H;           bias = fc_b[tid]; }
            else            { wrow = reg_w + (tid - NCLS) * H; bias = reg_b[tid - NCLS]; }
            float a = bias;
#pragma unroll 10
            for (int k = 0; k < H; ++k) a += wrow[k] * xr[k];
            out[tid] = a;
        }
        return;
    }
}

extern "C" void kernel_launch(void* const* d_in, const int* in_sizes, int n_in,
                              void* d_out, int out_size) {
    const float* x        = (const float*)d_in[0];
    const float* b_wih    = (const float*)d_in[1];
    const float* b_whh    = (const float*)d_in[2];
    const float* b_bih    = (const float*)d_in[3];
    const float* b_bhh    = (const float*)d_in[4];
    const float* gw_ih    = (const float*)d_in[5];
    const float* gw_hh    = (const float*)d_in[6];
    const float* gb_ih    = (const float*)d_in[7];
    const float* gb_hh    = (const float*)d_in[8];
    const float* g3_wih   = (const float*)d_in[9];
    const float* g3_whh   = (const float*)d_in[10];
    const float* g3_bih   = (const float*)d_in[11];
    const float* g3_bhh   = (const float*)d_in[12];
    const float* bn_gamma = (const float*)d_in[13];
    const float* bn_beta  = (const float*)d_in[14];
    const float* bn_mean  = (const float*)d_in[15];
    const float* bn_var   = (const float*)d_in[16];
    const float* fc_w     = (const float*)d_in[17];
    const float* fc_b     = (const float*)d_in[18];
    const float* reg_w    = (const float*)d_in[19];
    const float* reg_b    = (const float*)d_in[20];
    float* out = (float*)d_out;

    const int smem_bytes = (RPC * 164 + CC * RPC + RPC + 2 * H + RPC) * (int)sizeof(float);
    cudaFuncSetAttribute(spectral_kernel,
                         cudaFuncAttributeMaxDynamicSharedMemorySize, smem_bytes);

    pack_kernel<<<(PACK_F4 + 255) / 256, 256>>>(
        (const float4*)g3_wih, (const float4*)g3_whh, (const float4*)b_whh);
    spectral_kernel<<<NBLK, NT, smem_bytes>>>(
        x, b_wih, b_bih, b_bhh,
        gw_ih, gw_hh, gb_ih, gb_hh,
        g3_bih, g3_bhh,
        bn_gamma, bn_beta, bn_mean, bn_var,
        fc_w, fc_b, reg_w, reg_b, out);
}

// round 9
// speedup vs baseline: 1.4416x; 1.0253x over previous
#include <cuda_runtime.h>
#include <math.h>
#include <stdint.h>

#define H    160
#define H3   480
#define CC   200
#define TT   20
#define NCH  10
#define NL   160
#define NCLS 16
#define HS   40
#define RPC  120
#define NT   512
#define NBLK 68
#define FULL 160

#define NFLAGS ((NL + 1) * NCH + 1)
#define GDONE_IDX ((NL + 1) * NCH)
#define DONE_IDX(l, t) ((l) * NCH + (t))

/* packed weights: g3 wih chunks [0,640), g3 whh chunks [640,1280), branch [1280,1300) */
#define G3_F4   (1280 * 4800)
#define BR_F4   (20 * 9600)
#define PACK_F4 (G3_F4 + BR_F4)

__device__ float4 g_pack[PACK_F4];
__device__ float  g_S[(NL + 1) * NCH * H];
__device__ float  g_xl[H];
__device__ int    g_flags[NFLAGS];

typedef unsigned long long ull;

__device__ __forceinline__ float sigm(float v)   { return __fdividef(1.f, 1.f + __expf(-v)); }
__device__ __forceinline__ float tanh_f(float v) { return __fdividef(2.f, 1.f + __expf(-2.f * v)) - 1.f; }

__device__ __forceinline__ void poll_ge(const int* f, int tgt) {
    int v;
    do {
        asm volatile("ld.acquire.gpu.s32 %0, [%1];" : "=r"(v) : "l"(f) : "memory");
    } while (v < tgt);
}
__device__ __forceinline__ void red_release(int* f, int val) {
    asm volatile("red.release.gpu.add.s32 [%0], %1;" :: "l"(f), "r"(val) : "memory");
}

__device__ __forceinline__ uint32_t smem_u32(const void* p) {
    uint32_t a;
    asm("{ .reg .u64 t; cvta.to.shared.u64 t, %1; cvt.u32.u64 %0, t; }" : "=r"(a) : "l"(p));
    return a;
}
__device__ __forceinline__ void st_cluster_f32(uint32_t laddr, int rank, float v) {
    uint32_t r;
    asm("mapa.shared::cluster.u32 %0, %1, %2;" : "=r"(r) : "r"(laddr), "r"(rank));
    asm volatile("st.shared::cluster.f32 [%0], %1;" :: "r"(r), "f"(v) : "memory");
}
#define CLUSTER_SYNC() do { \
    asm volatile("barrier.cluster.arrive.aligned;" ::: "memory"); \
    asm volatile("barrier.cluster.wait.aligned;"   ::: "memory"); } while (0)

__device__ __forceinline__ ull pack2(float x, float y) {
    ull u; asm("mov.b64 %0, {%1, %2};" : "=l"(u) : "f"(x), "f"(y)); return u;
}
__device__ __forceinline__ void fma2(ull& acc, ull a, ull b) {
    asm("fma.rn.f32x2 %0, %1, %2, %0;" : "+l"(acc) : "l"(a), "l"(b));
}
__device__ __forceinline__ float upsum(ull a0, ull a1) {
    float l0, h0, l1, h1;
    asm("mov.b64 {%0, %1}, %2;" : "=f"(l0), "=f"(h0) : "l"(a0));
    asm("mov.b64 {%0, %1}, %2;" : "=f"(l1), "=f"(h1) : "l"(a1));
    return (l0 + h0) + (l1 + h1);
}

/* ---------- pack kernel (also zeroes flags) ---------- */
__global__ void pack_kernel(const float4* __restrict__ wih,
                            const float4* __restrict__ whh,
                            const float4* __restrict__ bwhh) {
    int id = blockIdx.x * blockDim.x + threadIdx.x;
    if (id < NFLAGS) g_flags[id] = 0;
    if (id >= PACK_F4) return;
    float4 v;
    if (id < G3_F4) {
        int m      = id / (640 * 4800);
        int rem    = id - m * (640 * 4800);
        int chunk  = rem / 4800;
        int within = rem - chunk * 4800;
        int i4 = within / 480, tid = within - i4 * 480;
        int l = chunk >> 2, c = chunk & 3;
        int q = tid >> 2, qk = tid & 3;
        int jrow = (q / HS) * H + c * HS + (q % HS);
        int k4 = qk * 10 + i4;
        const float4* src = (m == 0) ? wih : whh;
        v = src[((size_t)l * H3 + jrow) * 40 + k4];
    } else {
        int id2    = id - G3_F4;
        int chunk  = id2 / 9600;
        int within = id2 - chunk * 9600;
        int i4 = within / 480, tid = within - i4 * 480;
        int b = chunk >> 1, hh = chunk & 1;
        int qk2 = tid & 1, gi = tid >> 1;
        int g = gi / 80, ip = gi - g * 80;
        int j = g * H + hh * 80 + ip;
        int k4 = qk2 * 20 + i4;
        v = bwhh[((size_t)b * H3 + j) * 40 + k4];
    }
    g_pack[id] = v;
}

/* ---------- main persistent kernel ---------- */
__global__ void __launch_bounds__(NT, 1) __cluster_dims__(4, 1, 1)
spectral_kernel(
    const float* __restrict__ x,
    const float* __restrict__ b_wih, const float* __restrict__ b_bih,
    const float* __restrict__ b_bhh,
    const float* __restrict__ gw_ih, const float* __restrict__ gw_hh,
    const float* __restrict__ gb_ih, const float* __restrict__ gb_hh,
    const float* __restrict__ g3_bih, const float* __restrict__ g3_bhh,
    const float* __restrict__ bn_gamma, const float* __restrict__ bn_beta,
    const float* __restrict__ bn_mean, const float* __restrict__ bn_var,
    const float* __restrict__ fc_w, const float* __restrict__ fc_b,
    const float* __restrict__ reg_w, const float* __restrict__ reg_b,
    float* __restrict__ out)
{
    extern __shared__ float sm[];
    const int tid = threadIdx.x;
    const int blk = blockIdx.x;
    const float4* packW = g_pack;
    const bool dotw = (tid < 480);

    /* ============ g3 wavefront: blocks 0..39 (cluster = time group) ======== */
    if (blk < 40) {
        const int t = blk >> 2;
        const int c = blk & 3;
        const int q  = tid >> 2;
        const int qk = tid & 3;
        const int jrow = dotw ? ((q / HS) * H + c * HS + (q % HS)) : 0;

        float* xin2  = sm;                 /* [2][H] */
        float* hprev = sm + 2 * H;         /* [H]    */
        float* xps   = sm + 3 * H;         /* [RPC]  */
        float* hps   = xps + RPC;          /* [RPC]  */
        const uint32_t xin_base = smem_u32(xin2);

        if (tid < H) hprev[tid] = 0.f;
        CLUSTER_SYNC();   /* siblings alive + hprev zeroed cluster-wide view */

        ull Wx[20], Wh[20];
        if (dotw) {   /* preload wih(0), whh(0) */
            size_t bx = (size_t)(0 * 4 + c) * 4800 + tid;
            size_t bh = (size_t)(640 + 0 * 4 + c) * 4800 + tid;
#pragma unroll
            for (int i4 = 0; i4 < 10; ++i4) {
                float4 f = __ldg(&packW[bx + i4 * 480]);
                Wx[2 * i4] = pack2(f.x, f.y); Wx[2 * i4 + 1] = pack2(f.z, f.w);
                float4 g = __ldg(&packW[bh + i4 * 480]);
                Wh[2 * i4] = pack2(g.x, g.y); Wh[2 * i4 + 1] = pack2(g.z, g.w);
            }
        }

        /* l=0 input: branch t output */
        if (tid == 0) poll_ge(&g_flags[DONE_IDX(0, t)], FULL);
        __syncthreads();
        if (tid < 40)
            *(float4*)&xin2[tid * 4] = __ldcg((const float4*)&g_S[t * H + tid * 4]);
        __syncthreads();

        for (int l = 0; l < NL; ++l) {
            const int cur = l & 1, nxt = cur ^ 1;
            float bih_v = 0.f, bhh_v = 0.f;
            float ax = 0.f;

            if (dotw) {
                if (qk == 0) {
                    bih_v = __ldg(&g3_bih[l * H3 + jrow]);
                    bhh_v = __ldg(&g3_bhh[l * H3 + jrow]);
                }
                /* phase X immediately: xin2[cur] valid since csync(l-1) */
                const float* xv = xin2 + cur * H + qk * HS;
                ull a0 = 0, a1 = 0;
#pragma unroll
                for (int i4 = 0; i4 < 10; ++i4) {
                    ulonglong2 hv = *(const ulonglong2*)(xv + i4 * 4);
                    fma2(a0, Wx[2 * i4], hv.x);
                    fma2(a1, Wx[2 * i4 + 1], hv.y);
                }
                ax = upsum(a0, a1);
            } else if (t > 0) {
                /* warp 15: poll + stage h_prev concurrently with Wx dot */
                if ((tid & 31) == 0) poll_ge(&g_flags[DONE_IDX(l + 1, t - 1)], FULL);
                __syncwarp();
                const int lane = tid - 480;
                const float4* src = (const float4*)&g_S[((size_t)(l + 1) * NCH + (t - 1)) * H];
                ((float4*)hprev)[lane] = __ldcg(src + lane);
                if (lane < 8) ((float4*)hprev)[32 + lane] = __ldcg(src + 32 + lane);
            }
            __syncthreads();                              /* B2: hprev staged */

            if (dotw) {
                const float* hv0 = hprev + qk * HS;
                ull a0 = 0, a1 = 0;
#pragma unroll
                for (int i4 = 0; i4 < 10; ++i4) {
                    ulonglong2 hv = *(const ulonglong2*)(hv0 + i4 * 4);
                    fma2(a0, Wh[2 * i4], hv.x);
                    fma2(a1, Wh[2 * i4 + 1], hv.y);
                }
                float ah = upsum(a0, a1);
                ax += __shfl_xor_sync(0xffffffffu, ax, 1);
                ah += __shfl_xor_sync(0xffffffffu, ah, 1);
                ax += __shfl_xor_sync(0xffffffffu, ax, 2);
                ah += __shfl_xor_sync(0xffffffffu, ah, 2);
                if (qk == 0) { xps[q] = ax + bih_v; hps[q] = ah + bhh_v; }
                /* prefetch l+1 weights (hidden behind gate + csync + next X) */
                if (l + 1 < NL) {
                    size_t bx = (size_t)((l + 1) * 4 + c) * 4800 + tid;
                    size_t bh = (size_t)(640 + (l + 1) * 4 + c) * 4800 + tid;
#pragma unroll
                    for (int i4 = 0; i4 < 10; ++i4) {
                        float4 f = __ldg(&packW[bx + i4 * 480]);
                        Wx[2 * i4] = pack2(f.x, f.y); Wx[2 * i4 + 1] = pack2(f.z, f.w);
                        float4 g = __ldg(&packW[bh + i4 * 480]);
                        Wh[2 * i4] = pack2(g.x, g.y); Wh[2 * i4 + 1] = pack2(g.z, g.w);
                    }
                }
            }
            __syncthreads();                              /* B3: xps/hps ready */

            if (tid < 40) {
                const int i = tid;
                float hp_i = hprev[c * HS + i];
                float r = sigm(xps[i]          + hps[i]);
                float z = sigm(xps[HS + i]     + hps[HS + i]);
                float n = tanh_f(xps[2*HS + i] + r * hps[2*HS + i]);
                float hn = (1.f - z) * n + z * hp_i;
                __stcg(&g_S[((size_t)(l + 1) * NCH + t) * H + c * HS + i], hn);
                red_release(&g_flags[DONE_IDX(l + 1, t)], 1);
                uint32_t a3 = xin_base + (uint32_t)(nxt * H + c * HS + i) * 4u;
#pragma unroll
                for (int r2 = 0; r2 < 4; ++r2) st_cluster_f32(a3, r2, hn);
            }
            CLUSTER_SYNC();   /* orders DSMEM xin2[nxt] + protects buffer reuse */
        }
        return;
    }

    /* ============ global GRU: blocks 40..43, weights in registers ========== */
    if (blk < 44) {
        const int c = blk - 40;

        float* xp_s  = sm;                       /* [CC*RPC]  */
        float* bhh_s = xp_s + CC * RPC;          /* [RPC]     */
        float* h2    = bhh_s + RPC;              /* [2][H]    */
        float* hpb   = h2 + 2 * H;               /* [RPC]     */
        const uint32_t h2_base = smem_u32(h2);

        const int q2 = tid >> 2;
        const int qk = tid & 3;
        const int j  = dotw ? ((q2 / HS) * H + c * HS + (q2 % HS)) : 0;

        ull W[20];
        if (dotw) {
            const float4* wr = (const float4*)&gw_hh[(size_t)j * H + qk * HS];
#pragma unroll
            for (int i4 = 0; i4 < 10; ++i4) {
                float4 f = __ldg(wr + i4);
                W[2 * i4] = pack2(f.x, f.y); W[2 * i4 + 1] = pack2(f.z, f.w);
            }
        }
        for (int idx = tid; idx < CC * RPC; idx += NT) {
            int s = idx / RPC, qq = idx - s * RPC;
            int jj = (qq / HS) * H + c * HS + (qq % HS);
            xp_s[idx] = x[s] * gw_ih[jj] + gb_ih[jj];
        }
        if (tid < RPC) {
            int jj = (tid / HS) * H + c * HS + (tid % HS);
            bhh_s[tid] = gb_hh[jj];
        }
        if (tid < 2 * H) h2[tid] = 0.f;
        __syncthreads();
        CLUSTER_SYNC();

        float hsum = 0.f;
        for (int s = 0; s < CC; ++s) {
            const int cur = s & 1, nxt = cur ^ 1;
            if (dotw) {
                const float* hv0 = h2 + cur * H + qk * HS;
                ull a0 = 0, a1 = 0;
#pragma unroll
                for (int i4 = 0; i4 < 10; ++i4) {
                    ulonglong2 hv = *(const ulonglong2*)(hv0 + i4 * 4);
                    fma2(a0, W[2 * i4], hv.x);
                    fma2(a1, W[2 * i4 + 1], hv.y);
                }
                float a = upsum(a0, a1);
                a += __shfl_xor_sync(0xffffffffu, a, 1);
                a += __shfl_xor_sync(0xffffffffu, a, 2);
                if (qk == 0) hpb[q2] = a + bhh_s[q2];
            }
            __syncthreads();
            if (tid < HS) {
                const float* xpt = xp_s + s * RPC;
                const int i = tid;
                float r = sigm(xpt[i]          + hpb[i]);
                float z = sigm(xpt[HS + i]     + hpb[HS + i]);
                float n = tanh_f(xpt[2*HS + i] + r * hpb[2*HS + i]);
                float hn = (1.f - z) * n + z * h2[cur * H + c * HS + i];
                hsum += hn;
                uint32_t a2 = h2_base + (uint32_t)(nxt * H + c * HS + i) * 4u;
#pragma unroll
                for (int r2 = 0; r2 < 4; ++r2) st_cluster_f32(a2, r2, hn);
            }
            CLUSTER_SYNC();
        }
        if (tid < HS) {
            __stcg(&g_xl[c * HS + tid], hsum * (1.f / CC));
            red_release(&g_flags[GDONE_IDX], 1);
        }
        return;
    }

    /* ============ branch GRUs: blocks 44..63 (2 CTAs per branch) =========== */
    if (blk < 64) {
        const int pairblk = blk - 44;
        const int b    = pairblk >> 1;
        const int hh   = pairblk & 1;
        const int rank = pairblk & 3;

        float* xp_s = sm;                      /* [TT*240]  */
        float* h2   = xp_s + TT * 240;         /* [2][H]    */
        float* hp_s = h2 + 2 * H;              /* [240]     */
        const uint32_t h2b = smem_u32(h2);

        const int qk2 = tid & 1;
        const int gi  = tid >> 1;
        const int g   = gi / 80;
        const int ip  = gi - g * 80;
        const int jrow = dotw ? (g * H + hh * 80 + ip) : 0;

        ull W[40];
        if (dotw) {
            size_t base = (size_t)G3_F4 + (size_t)(b * 2 + hh) * 9600 + tid;
#pragma unroll
            for (int i4 = 0; i4 < 20; ++i4) {
                float4 f = __ldg(&packW[base + i4 * 480]);
                W[2 * i4] = pack2(f.x, f.y); W[2 * i4 + 1] = pack2(f.z, f.w);
            }
        }
        float bhh_v = 0.f;
        if (dotw && qk2 == 0) bhh_v = __ldg(&b_bhh[b * H3 + jrow]);

        for (int idx = tid; idx < TT * 240; idx += NT) {
            int tt = idx / 240, lr = idx - tt * 240;
            int jj = (lr / 80) * H + hh * 80 + (lr % 80);
            xp_s[idx] = x[b * TT + tt] * b_wih[b * H3 + jj] + b_bih[b * H3 + jj];
        }
        if (tid < 2 * H) h2[tid] = 0.f;
        __syncthreads();
        CLUSTER_SYNC();

        for (int tt = 0; tt < TT; ++tt) {
            const int cur = tt & 1, nxt = cur ^ 1;
            if (dotw) {
                const float* hv0 = h2 + cur * H + qk2 * 80;
                ull a0 = 0, a1 = 0;
#pragma unroll
                for (int i4 = 0; i4 < 20; ++i4) {
                    ulonglong2 hv = *(const ulonglong2*)(hv0 + i4 * 4);
                    fma2(a0, W[2 * i4], hv.x);
                    fma2(a1, W[2 * i4 + 1], hv.y);
                }
                float a = upsum(a0, a1);
                a += __shfl_xor_sync(0xffffffffu, a, 1);
                if (qk2 == 0) hp_s[g * 80 + ip] = a + bhh_v;
            }
            __syncthreads();

            if (dotw && qk2 == 0 && gi < 80) {
                const int i = gi;
                const float* xpt = xp_s + tt * 240;
                float r = sigm(xpt[i]          + hp_s[i]);
                float z = sigm(xpt[80 + i]     + hp_s[80 + i]);
                float n = tanh_f(xpt[160 + i]  + r * hp_s[160 + i]);
                float hn = (1.f - z) * n + z * h2[cur * H + hh * 80 + i];
                uint32_t a3 = h2b + (uint32_t)(nxt * H + hh * 80 + i) * 4u;
                st_cluster_f32(a3, rank, hn);
                st_cluster_f32(a3, rank ^ 1, hn);
            }
            CLUSTER_SYNC();
        }
        if (tid < 80) {
            __stcg(&g_S[b * H + hh * 80 + tid], h2[0 * H + hh * 80 + tid]);
            red_release(&g_flags[DONE_IDX(0, b)], 1);
        }
        CLUSTER_SYNC();
        return;
    }

    /* ============ epilogue: block 64 (65..67 idle) ========================= */
    if (blk == 64) {
        if (tid == 0) {
            for (int tt = 0; tt < NCH; ++tt) poll_ge(&g_flags[DONE_IDX(NL, tt)], FULL);
            poll_ge(&g_flags[GDONE_IDX], FULL);
        }
        __syncthreads();

        float* xr = sm;
        if (tid < H) {
            float m = 0.f;
#pragma unroll
            for (int tt = 0; tt < NCH; ++tt) m += __ldcg(&g_S[(NL * NCH + tt) * H + tid]);
            m *= (1.f / NCH);
            m = fmaxf(m, 0.f);
            float xnew = __ldcg(&g_xl[tid]) * m;
            float xb = (xnew - bn_mean[tid]) * rsqrtf(bn_var[tid] + 1e-5f)
                       * bn_gamma[tid] + bn_beta[tid];
            xr[tid] = fmaxf(xb, 0.f);
        }
        __syncthreads();

        if (tid < NCLS + CC) {
            const float* wrow; float bias;
            if (tid < NCLS) { wrow = fc_w + tid * H;           bias = fc_b[tid]; }
            else            { wrow = reg_w + (tid - NCLS) * H; bias = reg_b[tid - NCLS]; }
            float a = bias;
#pragma unroll 10
            for (int k = 0; k < H; ++k) a += wrow[k] * xr[k];
            out[tid] = a;
        }
        return;
    }
}

extern "C" void kernel_launch(void* const* d_in, const int* in_sizes, int n_in,
                              void* d_out, int out_size) {
    const float* x        = (const float*)d_in[0];
    const float* b_wih    = (const float*)d_in[1];
    const float* b_whh    = (const float*)d_in[2];
    const float* b_bih    = (const float*)d_in[3];
    const float* b_bhh    = (const float*)d_in[4];
    const float* gw_ih    = (const float*)d_in[5];
    const float* gw_hh    = (const float*)d_in[6];
    const float* gb_ih    = (const float*)d_in[7];
    const float* gb_hh    = (const float*)d_in[8];
    const float* g3_wih   = (const float*)d_in[9];
    const float* g3_whh   = (const float*)d_in[10];
    const float* g3_bih   = (const float*)d_in[11];
    const float* g3_bhh   = (const float*)d_in[12];
    const float* bn_gamma = (const float*)d_in[13];
    const float* bn_beta  = (const float*)d_in[14];
    const float* bn_mean  = (const float*)d_in[15];
    const float* bn_var   = (const float*)d_in[16];
    const float* fc_w     = (const float*)d_in[17];
    const float* fc_b     = (const float*)d_in[18];
    const float* reg_w    = (const float*)d_in[19];
    const float* reg_b    = (const float*)d_in[20];
    float* out = (float*)d_out;

    /* global-GRU role smem: CC*RPC + RPC + 2H + RPC floats (~98 KB) */
    const int smem_bytes = (CC * RPC + RPC + 2 * H + RPC) * (int)sizeof(float);
    cudaFuncSetAttribute(spectral_kernel,
                         cudaFuncAttributeMaxDynamicSharedMemorySize, smem_bytes);

    pack_kernel<<<(PACK_F4 + 255) / 256, 256>>>(
        (const float4*)g3_wih, (const float4*)g3_whh, (const float4*)b_whh);
    spectral_kernel<<<NBLK, NT, smem_bytes>>>(
        x, b_wih, b_bih, b_bhh,
        gw_ih, gw_hh, gb_ih, gb_hh,
        g3_bih, g3_bhh,
        bn_gamma, bn_beta, bn_mean, bn_var,
        fc_w, fc_b, reg_w, reg_b, out);
}

// round 10
// speedup vs baseline: 1.6298x; 1.1306x over previous
#include <cuda_runtime.h>
#include <math.h>
#include <stdint.h>

#define H    160
#define H3   480
#define CC   200
#define TT   20
#define NCH  10
#define NL   160
#define NCLS 16
#define HSS  20          /* h-slice per CTA (8-way split) */
#define RPC  60          /* rows per CTA = 3*HSS */
#define NT   512
#define NBLK 120
#define FULL 160

#define NFLAGS ((NL + 1) * NCH + 1)
#define GDONE_IDX ((NL + 1) * NCH)
#define DONE_IDX(l, t) ((l) * NCH + (t))

/* packed weights: g3 wih chunks [0,1280), g3 whh chunks [1280,2560), branch after */
#define G3_F4   (2560 * 2400)          /* 6,144,000 float4 */
#define BR_F4   (20 * 9600)
#define PACK_F4 (G3_F4 + BR_F4)

__device__ float4 g_pack[PACK_F4];
__device__ float  g_S[(NL + 1) * NCH * H];
__device__ float  g_xl[H];
__device__ int    g_flags[NFLAGS];

typedef unsigned long long ull;

__device__ __forceinline__ float sigm(float v)   { return __fdividef(1.f, 1.f + __expf(-v)); }
__device__ __forceinline__ float tanh_f(float v) { return __fdividef(2.f, 1.f + __expf(-2.f * v)) - 1.f; }

__device__ __forceinline__ void poll_ge(const int* f, int tgt) {
    int v;
    do {
        asm volatile("ld.acquire.gpu.s32 %0, [%1];" : "=r"(v) : "l"(f) : "memory");
    } while (v < tgt);
}
__device__ __forceinline__ void red_release(int* f, int val) {
    asm volatile("red.release.gpu.add.s32 [%0], %1;" :: "l"(f), "r"(val) : "memory");
}

__device__ __forceinline__ uint32_t smem_u32(const void* p) {
    uint32_t a;
    asm("{ .reg .u64 t; cvta.to.shared.u64 t, %1; cvt.u32.u64 %0, t; }" : "=r"(a) : "l"(p));
    return a;
}
__device__ __forceinline__ void st_cluster_f32(uint32_t laddr, int rank, float v) {
    uint32_t r;
    asm("mapa.shared::cluster.u32 %0, %1, %2;" : "=r"(r) : "r"(laddr), "r"(rank));
    asm volatile("st.shared::cluster.f32 [%0], %1;" :: "r"(r), "f"(v) : "memory");
}
#define CLUSTER_SYNC() do { \
    asm volatile("barrier.cluster.arrive.aligned;" ::: "memory"); \
    asm volatile("barrier.cluster.wait.aligned;"   ::: "memory"); } while (0)

__device__ __forceinline__ ull pack2(float x, float y) {
    ull u; asm("mov.b64 %0, {%1, %2};" : "=l"(u) : "f"(x), "f"(y)); return u;
}
__device__ __forceinline__ void fma2(ull& acc, ull a, ull b) {
    asm("fma.rn.f32x2 %0, %1, %2, %0;" : "+l"(acc) : "l"(a), "l"(b));
}
__device__ __forceinline__ float upsum(ull a0, ull a1) {
    float l0, h0, l1, h1;
    asm("mov.b64 {%0, %1}, %2;" : "=f"(l0), "=f"(h0) : "l"(a0));
    asm("mov.b64 {%0, %1}, %2;" : "=f"(l1), "=f"(h1) : "l"(a1));
    return (l0 + h0) + (l1 + h1);
}

/* ---------- pack kernel (also zeroes flags) ---------- */
__global__ void pack_kernel(const float4* __restrict__ wih,
                            const float4* __restrict__ whh,
                            const float4* __restrict__ bwhh) {
    int id = blockIdx.x * blockDim.x + threadIdx.x;
    if (id < NFLAGS) g_flags[id] = 0;
    if (id >= PACK_F4) return;
    float4 v;
    if (id < G3_F4) {
        int chunkid = id / 2400;                 /* 0..2559 */
        int within  = id - chunkid * 2400;
        int i4 = within / 480, tid = within - i4 * 480;
        int m  = chunkid / 1280;
        int lc = chunkid - m * 1280;
        int l = lc >> 3, c = lc & 7;
        int q = tid >> 3, qk = tid & 7;
        int jrow = (q / HSS) * H + c * HSS + (q % HSS);
        int k4 = qk * 5 + i4;
        const float4* src = (m == 0) ? wih : whh;
        v = src[((size_t)l * H3 + jrow) * 40 + k4];
    } else {
        int id2    = id - G3_F4;
        int chunk  = id2 / 9600;
        int within = id2 - chunk * 9600;
        int i4 = within / 480, tid = within - i4 * 480;
        int b = chunk >> 1, hh = chunk & 1;
        int qk2 = tid & 1, gi = tid >> 1;
        int g = gi / 80, ip = gi - g * 80;
        int j = g * H + hh * 80 + ip;
        int k4 = qk2 * 20 + i4;
        v = bwhh[((size_t)b * H3 + j) * 40 + k4];
    }
    g_pack[id] = v;
}

/* ---------- main persistent kernel ---------- */
__global__ void __launch_bounds__(NT, 1) __cluster_dims__(8, 1, 1)
spectral_kernel(
    const float* __restrict__ x,
    const float* __restrict__ b_wih, const float* __restrict__ b_bih,
    const float* __restrict__ b_bhh,
    const float* __restrict__ gw_ih, const float* __restrict__ gw_hh,
    const float* __restrict__ gb_ih, const float* __restrict__ gb_hh,
    const float* __restrict__ g3_bih, const float* __restrict__ g3_bhh,
    const float* __restrict__ bn_gamma, const float* __restrict__ bn_beta,
    const float* __restrict__ bn_mean, const float* __restrict__ bn_var,
    const float* __restrict__ fc_w, const float* __restrict__ fc_b,
    const float* __restrict__ reg_w, const float* __restrict__ reg_b,
    float* __restrict__ out)
{
    extern __shared__ float sm[];
    const int tid = threadIdx.x;
    const int blk = blockIdx.x;
    const float4* packW = g_pack;
    const bool dotw = (tid < 480);

    /* ============ g3 wavefront: blocks 0..79 (cluster of 8 = time group) === */
    if (blk < 80) {
        const int t = blk >> 3;
        const int c = blk & 7;
        const int q  = tid >> 3;          /* 0..59  row within CTA slice */
        const int qk = tid & 7;           /* 0..7   k-eighth (20 elems)  */
        const int jrow = dotw ? ((q / HSS) * H + c * HSS + (q % HSS)) : 0;

        float* xin2  = sm;                 /* [2][H] */
        float* hprev = sm + 2 * H;         /* [H]    */
        float* xps   = sm + 3 * H;         /* [RPC]  */
        float* hps   = xps + RPC;          /* [RPC]  */
        const uint32_t xin_base = smem_u32(xin2);

        if (tid < H) hprev[tid] = 0.f;
        CLUSTER_SYNC();

        ull Wx[10], Wh[10];
        if (dotw) {   /* preload wih(0), whh(0) */
            size_t bx = (size_t)(0 * 8 + c) * 2400 + tid;
            size_t bh = (size_t)(1280 + 0 * 8 + c) * 2400 + tid;
#pragma unroll
            for (int i4 = 0; i4 < 5; ++i4) {
                float4 f = __ldg(&packW[bx + i4 * 480]);
                Wx[2 * i4] = pack2(f.x, f.y); Wx[2 * i4 + 1] = pack2(f.z, f.w);
                float4 g = __ldg(&packW[bh + i4 * 480]);
                Wh[2 * i4] = pack2(g.x, g.y); Wh[2 * i4 + 1] = pack2(g.z, g.w);
            }
        }

        /* l=0 input: branch t output */
        if (tid == 0) poll_ge(&g_flags[DONE_IDX(0, t)], FULL);
        __syncthreads();
        if (tid < 40)
            *(float4*)&xin2[tid * 4] = __ldcg((const float4*)&g_S[t * H + tid * 4]);
        __syncthreads();

        for (int l = 0; l < NL; ++l) {
            const int cur = l & 1, nxt = cur ^ 1;
            float bih_v = 0.f, bhh_v = 0.f;
            float ax = 0.f;

            if (dotw) {
                if (qk == 0) {
                    bih_v = __ldg(&g3_bih[l * H3 + jrow]);
                    bhh_v = __ldg(&g3_bhh[l * H3 + jrow]);
                }
                const float* xv = xin2 + cur * H + qk * HSS;
                ull a0 = 0, a1 = 0;
#pragma unroll
                for (int i4 = 0; i4 < 5; ++i4) {
                    ulonglong2 hv = *(const ulonglong2*)(xv + i4 * 4);
                    fma2(a0, Wx[2 * i4], hv.x);
                    fma2(a1, Wx[2 * i4 + 1], hv.y);
                }
                ax = upsum(a0, a1);
            } else if (t > 0) {
                /* warp 15: poll + stage h_prev while dot warps compute X */
                if ((tid & 31) == 0) poll_ge(&g_flags[DONE_IDX(l + 1, t - 1)], FULL);
                __syncwarp();
                const int lane = tid - 480;
                const float4* src = (const float4*)&g_S[((size_t)(l + 1) * NCH + (t - 1)) * H];
                ((float4*)hprev)[lane] = __ldcg(src + lane);
                if (lane < 8) ((float4*)hprev)[32 + lane] = __ldcg(src + 32 + lane);
            }
            __syncthreads();                              /* B2 */

            if (dotw) {
                const float* hv0 = hprev + qk * HSS;
                ull a0 = 0, a1 = 0;
#pragma unroll
                for (int i4 = 0; i4 < 5; ++i4) {
                    ulonglong2 hv = *(const ulonglong2*)(hv0 + i4 * 4);
                    fma2(a0, Wh[2 * i4], hv.x);
                    fma2(a1, Wh[2 * i4 + 1], hv.y);
                }
                float ah = upsum(a0, a1);
                ax += __shfl_xor_sync(0xffffffffu, ax, 1);
                ah += __shfl_xor_sync(0xffffffffu, ah, 1);
                ax += __shfl_xor_sync(0xffffffffu, ax, 2);
                ah += __shfl_xor_sync(0xffffffffu, ah, 2);
                ax += __shfl_xor_sync(0xffffffffu, ax, 4);
                ah += __shfl_xor_sync(0xffffffffu, ah, 4);
                if (qk == 0) { xps[q] = ax + bih_v; hps[q] = ah + bhh_v; }
                if (l + 1 < NL) {
                    size_t bx = (size_t)((l + 1) * 8 + c) * 2400 + tid;
                    size_t bh = (size_t)(1280 + (l + 1) * 8 + c) * 2400 + tid;
#pragma unroll
                    for (int i4 = 0; i4 < 5; ++i4) {
                        float4 f = __ldg(&packW[bx + i4 * 480]);
                        Wx[2 * i4] = pack2(f.x, f.y); Wx[2 * i4 + 1] = pack2(f.z, f.w);
                        float4 g = __ldg(&packW[bh + i4 * 480]);
                        Wh[2 * i4] = pack2(g.x, g.y); Wh[2 * i4 + 1] = pack2(g.z, g.w);
                    }
                }
            }
            __syncthreads();                              /* B3 */

            if (tid < HSS) {
                const int i = tid;
                float hp_i = hprev[c * HSS + i];
                float r = sigm(xps[i]            + hps[i]);
                float z = sigm(xps[HSS + i]      + hps[HSS + i]);
                float n = tanh_f(xps[2*HSS + i]  + r * hps[2*HSS + i]);
                float hn = (1.f - z) * n + z * hp_i;
                __stcg(&g_S[((size_t)(l + 1) * NCH + t) * H + c * HSS + i], hn);
                red_release(&g_flags[DONE_IDX(l + 1, t)], 1);
                uint32_t a3 = xin_base + (uint32_t)(nxt * H + c * HSS + i) * 4u;
#pragma unroll
                for (int r2 = 0; r2 < 8; ++r2) st_cluster_f32(a3, r2, hn);
            }
            CLUSTER_SYNC();
        }
        return;
    }

    /* ============ global GRU: blocks 80..87, one cluster, 8-way ============ */
    if (blk < 88) {
        const int c = blk - 80;

        float* xp_s  = sm;                       /* [CC*RPC] 48KB */
        float* bhh_s = xp_s + CC * RPC;          /* [RPC]    */
        float* h2    = bhh_s + RPC;              /* [2][H]   */
        float* hpb   = h2 + 2 * H;               /* [RPC]    */
        const uint32_t h2_base = smem_u32(h2);

        const int q2 = tid >> 3;
        const int qk = tid & 7;
        const int j  = dotw ? ((q2 / HSS) * H + c * HSS + (q2 % HSS)) : 0;

        ull W[10];
        if (dotw) {
            const float4* wr = (const float4*)&gw_hh[(size_t)j * H + qk * HSS];
#pragma unroll
            for (int i4 = 0; i4 < 5; ++i4) {
                float4 f = __ldg(wr + i4);
                W[2 * i4] = pack2(f.x, f.y); W[2 * i4 + 1] = pack2(f.z, f.w);
            }
        }
        for (int idx = tid; idx < CC * RPC; idx += NT) {
            int s = idx / RPC, qq = idx - s * RPC;
            int jj = (qq / HSS) * H + c * HSS + (qq % HSS);
            xp_s[idx] = x[s] * gw_ih[jj] + gb_ih[jj];
        }
        if (tid < RPC) {
            int jj = (tid / HSS) * H + c * HSS + (tid % HSS);
            bhh_s[tid] = gb_hh[jj];
        }
        if (tid < 2 * H) h2[tid] = 0.f;
        __syncthreads();
        CLUSTER_SYNC();

        float hsum = 0.f;
        for (int s = 0; s < CC; ++s) {
            const int cur = s & 1, nxt = cur ^ 1;
            if (dotw) {
                const float* hv0 = h2 + cur * H + qk * HSS;
                ull a0 = 0, a1 = 0;
#pragma unroll
                for (int i4 = 0; i4 < 5; ++i4) {
                    ulonglong2 hv = *(const ulonglong2*)(hv0 + i4 * 4);
                    fma2(a0, W[2 * i4], hv.x);
                    fma2(a1, W[2 * i4 + 1], hv.y);
                }
                float a = upsum(a0, a1);
                a += __shfl_xor_sync(0xffffffffu, a, 1);
                a += __shfl_xor_sync(0xffffffffu, a, 2);
                a += __shfl_xor_sync(0xffffffffu, a, 4);
                if (qk == 0) hpb[q2] = a + bhh_s[q2];
            }
            __syncthreads();
            if (tid < HSS) {
                const float* xpt = xp_s + s * RPC;
                const int i = tid;
                float r = sigm(xpt[i]            + hpb[i]);
                float z = sigm(xpt[HSS + i]      + hpb[HSS + i]);
                float n = tanh_f(xpt[2*HSS + i]  + r * hpb[2*HSS + i]);
                float hn = (1.f - z) * n + z * h2[cur * H + c * HSS + i];
                hsum += hn;
                uint32_t a2 = h2_base + (uint32_t)(nxt * H + c * HSS + i) * 4u;
#pragma unroll
                for (int r2 = 0; r2 < 8; ++r2) st_cluster_f32(a2, r2, hn);
            }
            CLUSTER_SYNC();
        }
        if (tid < HSS) {
            __stcg(&g_xl[c * HSS + tid], hsum * (1.f / CC));
            red_release(&g_flags[GDONE_IDX], 1);
        }
        return;
    }

    /* ============ branch GRUs: blocks 88..107 (2 CTAs/branch, 4 pairs/cluster) */
    if (blk < 108) {
        const int pairblk = blk - 88;
        const int b    = pairblk >> 1;
        const int hh   = pairblk & 1;
        const int rank = pairblk & 7;

        float* xp_s = sm;                      /* [TT*240]  */
        float* h2   = xp_s + TT * 240;         /* [2][H]    */
        float* hp_s = h2 + 2 * H;              /* [240]     */
        const uint32_t h2b = smem_u32(h2);

        const int qk2 = tid & 1;
        const int gi  = tid >> 1;
        const int g   = gi / 80;
        const int ip  = gi - g * 80;
        const int jrow = dotw ? (g * H + hh * 80 + ip) : 0;

        ull W[40];
        if (dotw) {
            size_t base = (size_t)G3_F4 + (size_t)(b * 2 + hh) * 9600 + tid;
#pragma unroll
            for (int i4 = 0; i4 < 20; ++i4) {
                float4 f = __ldg(&packW[base + i4 * 480]);
                W[2 * i4] = pack2(f.x, f.y); W[2 * i4 + 1] = pack2(f.z, f.w);
            }
        }
        float bhh_v = 0.f;
        if (dotw && qk2 == 0) bhh_v = __ldg(&b_bhh[b * H3 + jrow]);

        for (int idx = tid; idx < TT * 240; idx += NT) {
            int tt = idx / 240, lr = idx - tt * 240;
            int jj = (lr / 80) * H + hh * 80 + (lr % 80);
            xp_s[idx] = x[b * TT + tt] * b_wih[b * H3 + jj] + b_bih[b * H3 + jj];
        }
        if (tid < 2 * H) h2[tid] = 0.f;
        __syncthreads();
        CLUSTER_SYNC();                                    /* sync #1 */

        for (int tt = 0; tt < TT; ++tt) {
            const int cur = tt & 1, nxt = cur ^ 1;
            if (dotw) {
                const float* hv0 = h2 + cur * H + qk2 * 80;
                ull a0 = 0, a1 = 0;
#pragma unroll
                for (int i4 = 0; i4 < 20; ++i4) {
                    ulonglong2 hv = *(const ulonglong2*)(hv0 + i4 * 4);
                    fma2(a0, W[2 * i4], hv.x);
                    fma2(a1, W[2 * i4 + 1], hv.y);
                }
                float a = upsum(a0, a1);
                a += __shfl_xor_sync(0xffffffffu, a, 1);
                if (qk2 == 0) hp_s[g * 80 + ip] = a + bhh_v;
            }
            __syncthreads();

            if (dotw && qk2 == 0 && gi < 80) {
                const int i = gi;
                const float* xpt = xp_s + tt * 240;
                float r = sigm(xpt[i]          + hp_s[i]);
                float z = sigm(xpt[80 + i]     + hp_s[80 + i]);
                float n = tanh_f(xpt[160 + i]  + r * hp_s[160 + i]);
                float hn = (1.f - z) * n + z * h2[cur * H + hh * 80 + i];
                uint32_t a3 = h2b + (uint32_t)(nxt * H + hh * 80 + i) * 4u;
                st_cluster_f32(a3, rank, hn);
                st_cluster_f32(a3, rank ^ 1, hn);
            }
            CLUSTER_SYNC();                                /* syncs #2..#21 */
        }
        if (tid < 80) {
            __stcg(&g_S[b * H + hh * 80 + tid], h2[0 * H + hh * 80 + tid]);
            red_release(&g_flags[DONE_IDX(0, b)], 1);
        }
        CLUSTER_SYNC();                                    /* sync #22 */
        return;
    }

    /* ============ branch-cluster fillers: blocks 108..111 ================== */
    if (blk < 112) {
        for (int i = 0; i < TT + 2; ++i) CLUSTER_SYNC();   /* match 22 syncs */
        return;
    }

    /* ============ epilogue: block 112 (113..119 idle, no cluster ops) ====== */
    if (blk == 112) {
        if (tid == 0) {
            for (int tt = 0; tt < NCH; ++tt) poll_ge(&g_flags[DONE_IDX(NL, tt)], FULL);
            poll_ge(&g_flags[GDONE_IDX], FULL);
        }
        __syncthreads();

        float* xr = sm;
        if (tid < H) {
            float m = 0.f;
#pragma unroll
            for (int tt = 0; tt < NCH; ++tt) m += __ldcg(&g_S[(NL * NCH + tt) * H + tid]);
            m *= (1.f / NCH);
            m = fmaxf(m, 0.f);
            float xnew = __ldcg(&g_xl[tid]) * m;
            float xb = (xnew - bn_mean[tid]) * rsqrtf(bn_var[tid] + 1e-5f)
                       * bn_gamma[tid] + bn_beta[tid];
            xr[tid] = fmaxf(xb, 0.f);
        }
        __syncthreads();

        if (tid < NCLS + CC) {
            const float* wrow; float bias;
            if (tid < NCLS) { wrow = fc_w + tid * H;           bias = fc_b[tid]; }
            else            { wrow = reg_w + (tid - NCLS) * H; bias = reg_b[tid - NCLS]; }
            float a = bias;
#pragma unroll 10
            for (int k = 0; k < H; ++k) a += wrow[k] * xr[k];
            out[tid] = a;
        }
        return;
    }
}

extern "C" void kernel_launch(void* const* d_in, const int* in_sizes, int n_in,
                              void* d_out, int out_size) {
    const float* x        = (const float*)d_in[0];
    const float* b_wih    = (const float*)d_in[1];
    const float* b_whh    = (const float*)d_in[2];
    const float* b_bih    = (const float*)d_in[3];
    const float* b_bhh    = (const float*)d_in[4];
    const float* gw_ih    = (const float*)d_in[5];
    const float* gw_hh    = (const float*)d_in[6];
    const float* gb_ih    = (const float*)d_in[7];
    const float* gb_hh    = (const float*)d_in[8];
    const float* g3_wih   = (const float*)d_in[9];
    const float* g3_whh   = (const float*)d_in[10];
    const float* g3_bih   = (const float*)d_in[11];
    const float* g3_bhh   = (const float*)d_in[12];
    const float* bn_gamma = (const float*)d_in[13];
    const float* bn_beta  = (const float*)d_in[14];
    const float* bn_mean  = (const float*)d_in[15];
    const float* bn_var   = (const float*)d_in[16];
    const float* fc_w     = (const float*)d_in[17];
    const float* fc_b     = (const float*)d_in[18];
    const float* reg_w    = (const float*)d_in[19];
    const float* reg_b    = (const float*)d_in[20];
    float* out = (float*)d_out;

    /* max role smem: global GRU = CC*RPC + RPC + 2H + RPC floats (~50KB) */
    const int smem_bytes = (CC * RPC + RPC + 2 * H + RPC) * (int)sizeof(float);
    cudaFuncSetAttribute(spectral_kernel,
                         cudaFuncAttributeMaxDynamicSharedMemorySize, smem_bytes);

    pack_kernel<<<(PACK_F4 + 255) / 256, 256>>>(
        (const float4*)g3_wih, (const float4*)g3_whh, (const float4*)b_whh);
    spectral_kernel<<<NBLK, NT, smem_bytes>>>(
        x, b_wih, b_bih, b_bhh,
        gw_ih, gw_hh, gb_ih, gb_hh,
        g3_bih, g3_bhh,
        bn_gamma, bn_beta, bn_mean, bn_var,
        fc_w, fc_b, reg_w, reg_b, out);
}

// round 11
// speedup vs baseline: 2.1991x; 1.3493x over previous
#include <cuda_runtime.h>
#include <math.h>
#include <stdint.h>

#define H    160
#define H3   480
#define CC   200
#define TT   20
#define NCH  10
#define NL   160
#define NCLS 16
#define HSS  20          /* h-slice per CTA (8-way split) */
#define RPC  60          /* rows per CTA = 3*HSS */
#define NT   512
#define NBLK 120
#define FULL 160

#define NFLAGS ((NL + 1) * NCH + 1)
#define GDONE_IDX ((NL + 1) * NCH)
#define DONE_IDX(l, t) ((l) * NCH + (t))

/* packed weights: g3 wih chunks [0,1280), g3 whh chunks [1280,2560), branch after */
#define G3_F4   (2560 * 2400)          /* 6,144,000 float4 */
#define BR_F4   (20 * 9600)
#define PACK_F4 (G3_F4 + BR_F4)

__device__ float4 g_pack[PACK_F4];
__device__ float  g_S[(NL + 1) * NCH * H];
__device__ float  g_xl[H];
__device__ int    g_flags[NFLAGS];

typedef unsigned long long ull;

__device__ __forceinline__ float sigm(float v)   { return __fdividef(1.f, 1.f + __expf(-v)); }
__device__ __forceinline__ float tanh_f(float v) { return __fdividef(2.f, 1.f + __expf(-2.f * v)) - 1.f; }

__device__ __forceinline__ void poll_ge(const int* f, int tgt) {
    int v;
    do {
        asm volatile("ld.acquire.gpu.s32 %0, [%1];" : "=r"(v) : "l"(f) : "memory");
    } while (v < tgt);
}
__device__ __forceinline__ void red_release(int* f, int val) {
    asm volatile("red.release.gpu.add.s32 [%0], %1;" :: "l"(f), "r"(val) : "memory");
}

__device__ __forceinline__ uint32_t smem_u32(const void* p) {
    uint32_t a;
    asm("{ .reg .u64 t; cvta.to.shared.u64 t, %1; cvt.u32.u64 %0, t; }" : "=r"(a) : "l"(p));
    return a;
}
__device__ __forceinline__ void st_cluster_f32(uint32_t laddr, int rank, float v) {
    uint32_t r;
    asm("mapa.shared::cluster.u32 %0, %1, %2;" : "=r"(r) : "r"(laddr), "r"(rank));
    asm volatile("st.shared::cluster.f32 [%0], %1;" :: "r"(r), "f"(v) : "memory");
}
#define CLUSTER_SYNC() do { \
    asm volatile("barrier.cluster.arrive.aligned;" ::: "memory"); \
    asm volatile("barrier.cluster.wait.aligned;"   ::: "memory"); } while (0)
#define CLUSTER_ARRIVE() asm volatile("barrier.cluster.arrive;" ::: "memory")
#define CLUSTER_WAIT()   asm volatile("barrier.cluster.wait;"   ::: "memory")
#define BAR_DOT()        asm volatile("bar.sync 1, 480;" ::: "memory")

__device__ __forceinline__ ull pack2(float x, float y) {
    ull u; asm("mov.b64 %0, {%1, %2};" : "=l"(u) : "f"(x), "f"(y)); return u;
}
__device__ __forceinline__ void fma2(ull& acc, ull a, ull b) {
    asm("fma.rn.f32x2 %0, %1, %2, %0;" : "+l"(acc) : "l"(a), "l"(b));
}
__device__ __forceinline__ float upsum(ull a0, ull a1) {
    float l0, h0, l1, h1;
    asm("mov.b64 {%0, %1}, %2;" : "=f"(l0), "=f"(h0) : "l"(a0));
    asm("mov.b64 {%0, %1}, %2;" : "=f"(l1), "=f"(h1) : "l"(a1));
    return (l0 + h0) + (l1 + h1);
}

/* ---------- pack kernel (also zeroes flags) ---------- */
__global__ void pack_kernel(const float4* __restrict__ wih,
                            const float4* __restrict__ whh,
                            const float4* __restrict__ bwhh) {
    int id = blockIdx.x * blockDim.x + threadIdx.x;
    if (id < NFLAGS) g_flags[id] = 0;
    if (id >= PACK_F4) return;
    float4 v;
    if (id < G3_F4) {
        int chunkid = id / 2400;                 /* 0..2559 */
        int within  = id - chunkid * 2400;
        int i4 = within / 480, tid = within - i4 * 480;
        int m  = chunkid / 1280;
        int lc = chunkid - m * 1280;
        int l = lc >> 3, c = lc & 7;
        int q = tid >> 3, qk = tid & 7;
        int jrow = (q / HSS) * H + c * HSS + (q % HSS);
        int k4 = qk * 5 + i4;
        const float4* src = (m == 0) ? wih : whh;
        v = src[((size_t)l * H3 + jrow) * 40 + k4];
    } else {
        int id2    = id - G3_F4;
        int chunk  = id2 / 9600;
        int within = id2 - chunk * 9600;
        int i4 = within / 480, tid = within - i4 * 480;
        int b = chunk >> 1, hh = chunk & 1;
        int qk2 = tid & 1, gi = tid >> 1;
        int g = gi / 80, ip = gi - g * 80;
        int j = g * H + hh * 80 + ip;
        int k4 = qk2 * 20 + i4;
        v = bwhh[((size_t)b * H3 + j) * 40 + k4];
    }
    g_pack[id] = v;
}

/* ---------- main persistent kernel ---------- */
__global__ void __launch_bounds__(NT, 1) __cluster_dims__(8, 1, 1)
spectral_kernel(
    const float* __restrict__ x,
    const float* __restrict__ b_wih, const float* __restrict__ b_bih,
    const float* __restrict__ b_bhh,
    const float* __restrict__ gw_ih, const float* __restrict__ gw_hh,
    const float* __restrict__ gb_ih, const float* __restrict__ gb_hh,
    const float* __restrict__ g3_bih, const float* __restrict__ g3_bhh,
    const float* __restrict__ bn_gamma, const float* __restrict__ bn_beta,
    const float* __restrict__ bn_mean, const float* __restrict__ bn_var,
    const float* __restrict__ fc_w, const float* __restrict__ fc_b,
    const float* __restrict__ reg_w, const float* __restrict__ reg_b,
    float* __restrict__ out)
{
    extern __shared__ float sm[];
    const int tid = threadIdx.x;
    const int blk = blockIdx.x;
    const float4* packW = g_pack;
    const bool dotw = (tid < 480);

    /* ============ g3 wavefront: blocks 0..79 (cluster of 8 = time group) === */
    if (blk < 80) {
        const int t = blk >> 3;
        const int c = blk & 7;
        const int q  = tid >> 3;          /* 0..59  row within CTA slice */
        const int qk = tid & 7;           /* 0..7   k-eighth (20 elems)  */
        const int jrow = dotw ? ((q / HSS) * H + c * HSS + (q % HSS)) : 0;

        float* xin2 = sm;                 /* [2][H] */
        float* hbuf = sm + 2 * H;         /* [2][H] double-buffered h_prev */
        float* xps  = sm + 4 * H;         /* [RPC]  */
        float* hps  = xps + RPC;          /* [RPC]  */
        const uint32_t xin_base = smem_u32(xin2);

        if (tid < 2 * H) hbuf[tid] = 0.f;
        CLUSTER_SYNC();

        ull Wx[10], Wh[10];
        float bih_c = 0.f, bhh_c = 0.f;
        if (dotw) {   /* preload wih(0), whh(0), biases(0) */
            size_t bx = (size_t)(0 * 8 + c) * 2400 + tid;
            size_t bh = (size_t)(1280 + 0 * 8 + c) * 2400 + tid;
#pragma unroll
            for (int i4 = 0; i4 < 5; ++i4) {
                float4 f = __ldg(&packW[bx + i4 * 480]);
                Wx[2 * i4] = pack2(f.x, f.y); Wx[2 * i4 + 1] = pack2(f.z, f.w);
                float4 g = __ldg(&packW[bh + i4 * 480]);
                Wh[2 * i4] = pack2(g.x, g.y); Wh[2 * i4 + 1] = pack2(g.z, g.w);
            }
            if (qk == 0) { bih_c = __ldg(&g3_bih[jrow]); bhh_c = __ldg(&g3_bhh[jrow]); }
        }

        /* initial staging: xin[0] from branch; hbuf[0] = S(1,t-1) */
        if (tid == 0) poll_ge(&g_flags[DONE_IDX(0, t)], FULL);
        if (t > 0 && tid == 480) poll_ge(&g_flags[DONE_IDX(1, t - 1)], FULL);
        __syncthreads();
        if (tid < 40)
            *(float4*)&xin2[tid * 4] = __ldcg((const float4*)&g_S[t * H + tid * 4]);
        if (t > 0 && !dotw) {
            const int lane = tid - 480;
            const float4* src = (const float4*)&g_S[((size_t)1 * NCH + (t - 1)) * H];
            ((float4*)hbuf)[lane] = __ldcg(src + lane);
            if (lane < 8) ((float4*)hbuf)[32 + lane] = __ldcg(src + 32 + lane);
        }
        __syncthreads();

        for (int l = 0; l < NL; ++l) {
            const int cur = l & 1, nxt = cur ^ 1;

            if (dotw) {
                /* fused X + H dots: both xin2[cur] and hbuf[cur] ready */
                const float* xv  = xin2 + cur * H + qk * HSS;
                const float* hv0 = hbuf + cur * H + qk * HSS;
                ull a0 = 0, a1 = 0, b0 = 0, b1 = 0;
#pragma unroll
                for (int i4 = 0; i4 < 5; ++i4) {
                    ulonglong2 xh = *(const ulonglong2*)(xv + i4 * 4);
                    ulonglong2 hh = *(const ulonglong2*)(hv0 + i4 * 4);
                    fma2(a0, Wx[2 * i4], xh.x); fma2(a1, Wx[2 * i4 + 1], xh.y);
                    fma2(b0, Wh[2 * i4], hh.x); fma2(b1, Wh[2 * i4 + 1], hh.y);
                }
                float ax = upsum(a0, a1);
                float ah = upsum(b0, b1);
                ax += __shfl_xor_sync(0xffffffffu, ax, 1);
                ah += __shfl_xor_sync(0xffffffffu, ah, 1);
                ax += __shfl_xor_sync(0xffffffffu, ax, 2);
                ah += __shfl_xor_sync(0xffffffffu, ah, 2);
                ax += __shfl_xor_sync(0xffffffffu, ax, 4);
                ah += __shfl_xor_sync(0xffffffffu, ah, 4);
                if (qk == 0) { xps[q] = ax + bih_c; hps[q] = ah + bhh_c; }
                BAR_DOT();                       /* dots -> gate (480 threads) */

                if (tid < HSS) {
                    const int i = tid;
                    float hp_i = hbuf[cur * H + c * HSS + i];
                    float r = sigm(xps[i]            + hps[i]);
                    float z = sigm(xps[HSS + i]      + hps[HSS + i]);
                    float n = tanh_f(xps[2*HSS + i]  + r * hps[2*HSS + i]);
                    float hn = (1.f - z) * n + z * hp_i;
                    __stcg(&g_S[((size_t)(l + 1) * NCH + t) * H + c * HSS + i], hn);
                    red_release(&g_flags[DONE_IDX(l + 1, t)], 1);
                    uint32_t a3 = xin_base + (uint32_t)(nxt * H + c * HSS + i) * 4u;
#pragma unroll
                    for (int r2 = 0; r2 < 8; ++r2) st_cluster_f32(a3, r2, hn);
                }
                CLUSTER_ARRIVE();
                /* prefetch weights + biases for l+1 between arrive and wait */
                if (l + 1 < NL) {
                    size_t bx = (size_t)((l + 1) * 8 + c) * 2400 + tid;
                    size_t bh = (size_t)(1280 + (l + 1) * 8 + c) * 2400 + tid;
#pragma unroll
                    for (int i4 = 0; i4 < 5; ++i4) {
                        float4 f = __ldg(&packW[bx + i4 * 480]);
                        Wx[2 * i4] = pack2(f.x, f.y); Wx[2 * i4 + 1] = pack2(f.z, f.w);
                        float4 g = __ldg(&packW[bh + i4 * 480]);
                        Wh[2 * i4] = pack2(g.x, g.y); Wh[2 * i4 + 1] = pack2(g.z, g.w);
                    }
                    if (qk == 0) {
                        bih_c = __ldg(&g3_bih[(l + 1) * H3 + jrow]);
                        bhh_c = __ldg(&g3_bhh[(l + 1) * H3 + jrow]);
                    }
                }
                CLUSTER_WAIT();
            } else {
                /* warp15: prefetch h for layer l+1 into hbuf[nxt] */
                if (t > 0 && l + 2 <= NL) {
                    if (tid == 480) poll_ge(&g_flags[DONE_IDX(l + 2, t - 1)], FULL);
                    __syncwarp();
                    const int lane = tid - 480;
                    const float4* src =
                        (const float4*)&g_S[((size_t)(l + 2) * NCH + (t - 1)) * H];
                    ((float4*)(hbuf + nxt * H))[lane] = __ldcg(src + lane);
                    if (lane < 8)
                        ((float4*)(hbuf + nxt * H))[32 + lane] = __ldcg(src + 32 + lane);
                }
                CLUSTER_ARRIVE();
                CLUSTER_WAIT();
            }
        }
        return;
    }

    /* ============ global GRU: blocks 80..87, one cluster, 8-way ============ */
    if (blk < 88) {
        const int c = blk - 80;

        float* xp_s  = sm;                       /* [CC*RPC] 48KB */
        float* bhh_s = xp_s + CC * RPC;          /* [RPC]    */
        float* h2    = bhh_s + RPC;              /* [2][H]   */
        float* hpb   = h2 + 2 * H;               /* [RPC]    */
        const uint32_t h2_base = smem_u32(h2);

        const int q2 = tid >> 3;
        const int qk = tid & 7;
        const int j  = dotw ? ((q2 / HSS) * H + c * HSS + (q2 % HSS)) : 0;

        ull W[10];
        if (dotw) {
            const float4* wr = (const float4*)&gw_hh[(size_t)j * H + qk * HSS];
#pragma unroll
            for (int i4 = 0; i4 < 5; ++i4) {
                float4 f = __ldg(wr + i4);
                W[2 * i4] = pack2(f.x, f.y); W[2 * i4 + 1] = pack2(f.z, f.w);
            }
        }
        for (int idx = tid; idx < CC * RPC; idx += NT) {
            int s = idx / RPC, qq = idx - s * RPC;
            int jj = (qq / HSS) * H + c * HSS + (qq % HSS);
            xp_s[idx] = x[s] * gw_ih[jj] + gb_ih[jj];
        }
        if (tid < RPC) {
            int jj = (tid / HSS) * H + c * HSS + (tid % HSS);
            bhh_s[tid] = gb_hh[jj];
        }
        if (tid < 2 * H) h2[tid] = 0.f;
        __syncthreads();
        CLUSTER_SYNC();

        float hsum = 0.f;
        for (int s = 0; s < CC; ++s) {
            const int cur = s & 1, nxt = cur ^ 1;
            if (dotw) {
                const float* hv0 = h2 + cur * H + qk * HSS;
                ull a0 = 0, a1 = 0;
#pragma unroll
                for (int i4 = 0; i4 < 5; ++i4) {
                    ulonglong2 hv = *(const ulonglong2*)(hv0 + i4 * 4);
                    fma2(a0, W[2 * i4], hv.x);
                    fma2(a1, W[2 * i4 + 1], hv.y);
                }
                float a = upsum(a0, a1);
                a += __shfl_xor_sync(0xffffffffu, a, 1);
                a += __shfl_xor_sync(0xffffffffu, a, 2);
                a += __shfl_xor_sync(0xffffffffu, a, 4);
                if (qk == 0) hpb[q2] = a + bhh_s[q2];
            }
            __syncthreads();
            if (tid < HSS) {
                const float* xpt = xp_s + s * RPC;
                const int i = tid;
                float r = sigm(xpt[i]            + hpb[i]);
                float z = sigm(xpt[HSS + i]      + hpb[HSS + i]);
                float n = tanh_f(xpt[2*HSS + i]  + r * hpb[2*HSS + i]);
                float hn = (1.f - z) * n + z * h2[cur * H + c * HSS + i];
                hsum += hn;
                uint32_t a2 = h2_base + (uint32_t)(nxt * H + c * HSS + i) * 4u;
#pragma unroll
                for (int r2 = 0; r2 < 8; ++r2) st_cluster_f32(a2, r2, hn);
            }
            CLUSTER_SYNC();
        }
        if (tid < HSS) {
            __stcg(&g_xl[c * HSS + tid], hsum * (1.f / CC));
            red_release(&g_flags[GDONE_IDX], 1);
        }
        return;
    }

    /* ============ branch GRUs: blocks 88..107 (2 CTAs/branch, 4 pairs/cluster) */
    if (blk < 108) {
        const int pairblk = blk - 88;
        const int b    = pairblk >> 1;
        const int hh   = pairblk & 1;
        const int rank = pairblk & 7;

        float* xp_s = sm;                      /* [TT*240]  */
        float* h2   = xp_s + TT * 240;         /* [2][H]    */
        float* hp_s = h2 + 2 * H;              /* [240]     */
        const uint32_t h2b = smem_u32(h2);

        const int qk2 = tid & 1;
        const int gi  = tid >> 1;
        const int g   = gi / 80;
        const int ip  = gi - g * 80;
        const int jrow = dotw ? (g * H + hh * 80 + ip) : 0;

        ull W[40];
        if (dotw) {
            size_t base = (size_t)G3_F4 + (size_t)(b * 2 + hh) * 9600 + tid;
#pragma unroll
            for (int i4 = 0; i4 < 20; ++i4) {
                float4 f = __ldg(&packW[base + i4 * 480]);
                W[2 * i4] = pack2(f.x, f.y); W[2 * i4 + 1] = pack2(f.z, f.w);
            }
        }
        float bhh_v = 0.f;
        if (dotw && qk2 == 0) bhh_v = __ldg(&b_bhh[b * H3 + jrow]);

        for (int idx = tid; idx < TT * 240; idx += NT) {
            int tt = idx / 240, lr = idx - tt * 240;
            int jj = (lr / 80) * H + hh * 80 + (lr % 80);
            xp_s[idx] = x[b * TT + tt] * b_wih[b * H3 + jj] + b_bih[b * H3 + jj];
        }
        if (tid < 2 * H) h2[tid] = 0.f;
        __syncthreads();
        CLUSTER_SYNC();                                    /* sync #1 */

        for (int tt = 0; tt < TT; ++tt) {
            const int cur = tt & 1, nxt = cur ^ 1;
            if (dotw) {
                const float* hv0 = h2 + cur * H + qk2 * 80;
                ull a0 = 0, a1 = 0;
#pragma unroll
                for (int i4 = 0; i4 < 20; ++i4) {
                    ulonglong2 hv = *(const ulonglong2*)(hv0 + i4 * 4);
                    fma2(a0, W[2 * i4], hv.x);
                    fma2(a1, W[2 * i4 + 1], hv.y);
                }
                float a = upsum(a0, a1);
                a += __shfl_xor_sync(0xffffffffu, a, 1);
                if (qk2 == 0) hp_s[g * 80 + ip] = a + bhh_v;
            }
            __syncthreads();

            if (dotw && qk2 == 0 && gi < 80) {
                const int i = gi;
                const float* xpt = xp_s + tt * 240;
                float r = sigm(xpt[i]          + hp_s[i]);
                float z = sigm(xpt[80 + i]     + hp_s[80 + i]);
                float n = tanh_f(xpt[160 + i]  + r * hp_s[160 + i]);
                float hn = (1.f - z) * n + z * h2[cur * H + hh * 80 + i];
                uint32_t a3 = h2b + (uint32_t)(nxt * H + hh * 80 + i) * 4u;
                st_cluster_f32(a3, rank, hn);
                st_cluster_f32(a3, rank ^ 1, hn);
            }
            CLUSTER_SYNC();                                /* syncs #2..#21 */
        }
        if (tid < 80) {
            __stcg(&g_S[b * H + hh * 80 + tid], h2[0 * H + hh * 80 + tid]);
            red_release(&g_flags[DONE_IDX(0, b)], 1);
        }
        CLUSTER_SYNC();                                    /* sync #22 */
        return;
    }

    /* ============ branch-cluster fillers: blocks 108..111 ================== */
    if (blk < 112) {
        for (int i = 0; i < TT + 2; ++i) CLUSTER_SYNC();   /* match 22 syncs */
        return;
    }

    /* ============ epilogue: block 112 (113..119 idle, no cluster ops) ====== */
    if (blk == 112) {
        if (tid == 0) {
            for (int tt = 0; tt < NCH; ++tt) poll_ge(&g_flags[DONE_IDX(NL, tt)], FULL);
            poll_ge(&g_flags[GDONE_IDX], FULL);
        }
        __syncthreads();

        float* xr = sm;
        if (tid < H) {
            float m = 0.f;
#pragma unroll
            for (int tt = 0; tt < NCH; ++tt) m += __ldcg(&g_S[(NL * NCH + tt) * H + tid]);
            m *= (1.f / NCH);
            m = fmaxf(m, 0.f);
            float xnew = __ldcg(&g_xl[tid]) * m;
            float xb = (xnew - bn_mean[tid]) * rsqrtf(bn_var[tid] + 1e-5f)
                       * bn_gamma[tid] + bn_beta[tid];
            xr[tid] = fmaxf(xb, 0.f);
        }
        __syncthreads();

        if (tid < NCLS + CC) {
            const float* wrow; float bias;
            if (tid < NCLS) { wrow = fc_w + tid * H;           bias = fc_b[tid]; }
            else            { wrow = reg_w + (tid - NCLS) * H; bias = reg_b[tid - NCLS]; }
            float a = bias;
#pragma unroll 10
            for (int k = 0; k < H; ++k) a += wrow[k] * xr[k];
            out[tid] = a;
        }
        return;
    }
}

extern "C" void kernel_launch(void* const* d_in, const int* in_sizes, int n_in,
                              void* d_out, int out_size) {
    const float* x        = (const float*)d_in[0];
    const float* b_wih    = (const float*)d_in[1];
    const float* b_whh    = (const float*)d_in[2];
    const float* b_bih    = (const float*)d_in[3];
    const float* b_bhh    = (const float*)d_in[4];
    const float* gw_ih    = (const float*)d_in[5];
    const float* gw_hh    = (const float*)d_in[6];
    const float* gb_ih    = (const float*)d_in[7];
    const float* gb_hh    = (const float*)d_in[8];
    const float* g3_wih   = (const float*)d_in[9];
    const float* g3_whh   = (const float*)d_in[10];
    const float* g3_bih   = (const float*)d_in[11];
    const float* g3_bhh   = (const float*)d_in[12];
    const float* bn_gamma = (const float*)d_in[13];
    const float* bn_beta  = (const float*)d_in[14];
    const float* bn_mean  = (const float*)d_in[15];
    const float* bn_var   = (const float*)d_in[16];
    const float* fc_w     = (const float*)d_in[17];
    const float* fc_b     = (const float*)d_in[18];
    const float* reg_w    = (const float*)d_in[19];
    const float* reg_b    = (const float*)d_in[20];
    float* out = (float*)d_out;

    /* max role smem: global GRU = CC*RPC + RPC + 2H + RPC floats (~50KB) */
    const int smem_bytes = (CC * RPC + RPC + 2 * H + RPC) * (int)sizeof(float);
    cudaFuncSetAttribute(spectral_kernel,
                         cudaFuncAttributeMaxDynamicSharedMemorySize, smem_bytes);

    pack_kernel<<<(PACK_F4 + 255) / 256, 256>>>(
        (const float4*)g3_wih, (const float4*)g3_whh, (const float4*)b_whh);
    spectral_kernel<<<NBLK, NT, smem_bytes>>>(
        x, b_wih, b_bih, b_bhh,
        gw_ih, gw_hh, gb_ih, gb_hh,
        g3_bih, g3_bhh,
        bn_gamma, bn_beta, bn_mean, bn_var,
        fc_w, fc_b, reg_w, reg_b, out);
}